// round 1
// baseline (speedup 1.0000x reference)
#include <cuda_runtime.h>
#include <math.h>

#define NSTREAMS 2
#define NB 8
#define C_IN 256
#define HID 128
#define NTOK 2304     // 48*48
#define O3 384        // 3*HID
#define ATT_SCALE 0.0625f   // 256^-0.5

#define BM 64
#define BN 64
#define LDQ 133       // padded row stride for sQ/sK/sV (conflict-free: 133%32=5, coprime)
#define LDSS 65       // padded row stride for score tile

// ---------------- scratch (device globals; no allocs allowed) ----------------
__device__ float g_q[NSTREAMS][NB][HID][NTOK];   // channel-major
__device__ float g_k[NSTREAMS][NB][HID][NTOK];
__device__ float g_v[NSTREAMS][NB][HID][NTOK];
__device__ float g_h[NSTREAMS][NB][NTOK][HID];   // token-major (attn output)
__device__ float g_weff[NSTREAMS][HID][C_IN];    // head-folded output weight

// ---------------- embed: e = W x + b, split into q/k/v ----------------
// per batch: C[o][m] = sum_c w[o][c] * x[c][m],  o in [0,384), m in [0,2304)
__global__ void embed_kernel(const float* __restrict__ x0, const float* __restrict__ x1,
                             const float* __restrict__ w0, const float* __restrict__ b0,
                             const float* __restrict__ w1, const float* __restrict__ b1) {
    int z = blockIdx.z;            // s*NB + b
    int s = z / NB, b = z % NB;
    const float* x = (s == 0 ? x0 : x1) + (size_t)b * C_IN * NTOK;
    const float* w = (s == 0 ? w0 : w1);
    const float* bias = (s == 0 ? b0 : b1);
    int o0 = blockIdx.y * 64;
    int m0 = blockIdx.x * 64;

    __shared__ float sW[16 * 65];  // sW[cc][oo], padded
    __shared__ float sX[16 * 64];  // sX[cc][mm]

    int tid = threadIdx.x;
    int tx = tid & 15, ty = tid >> 4;
    float acc[4][4] = {};

    for (int k0 = 0; k0 < C_IN; k0 += 16) {
        for (int i = tid; i < 64 * 16; i += 256) {
            int oo = i >> 4, cc = i & 15;
            sW[cc * 65 + oo] = w[(size_t)(o0 + oo) * C_IN + k0 + cc];
        }
        for (int i = tid; i < 16 * 64; i += 256) {
            int cc = i >> 6, mm = i & 63;
            sX[cc * 64 + mm] = x[(size_t)(k0 + cc) * NTOK + m0 + mm];
        }
        __syncthreads();
#pragma unroll
        for (int kk = 0; kk < 16; kk++) {
            float wr[4], xr[4];
#pragma unroll
            for (int i = 0; i < 4; i++) wr[i] = sW[kk * 65 + ty * 4 + i];
#pragma unroll
            for (int j = 0; j < 4; j++) xr[j] = sX[kk * 64 + tx + 16 * j];
#pragma unroll
            for (int i = 0; i < 4; i++)
#pragma unroll
                for (int j = 0; j < 4; j++) acc[i][j] += wr[i] * xr[j];
        }
        __syncthreads();
    }
#pragma unroll
    for (int i = 0; i < 4; i++) {
        int o = o0 + ty * 4 + i;
        float bv = bias[o];
        float* dst;
        if (o < HID)          dst = &g_q[s][b][o][0];
        else if (o < 2 * HID) dst = &g_k[s][b][o - HID][0];
        else                  dst = &g_v[s][b][o - 2 * HID][0];
#pragma unroll
        for (int j = 0; j < 4; j++) {
            int m = m0 + tx + 16 * j;
            dst[m] = acc[i][j] + bv;
        }
    }
}

// ---------------- head-fold the output weight: [512,256] -> [128,256] ----------------
__global__ void weff_kernel(const float* __restrict__ w0, const float* __restrict__ w1) {
    int c = blockIdx.x;            // 0..127
    int s = blockIdx.y;
    const float* w = (s == 0 ? w0 : w1);
    int o = threadIdx.x;           // 0..255
    float acc = 0.f;
#pragma unroll
    for (int j = 0; j < 4; j++) acc += w[(size_t)(c + HID * j) * C_IN + o];
    g_weff[s][c][o] = acc;
}

// ---------------- flash attention (fp32) ----------------
// stream s output uses Q from stream 1-s, K/V from stream s.
// h[s][b][m][d] = sum_n softmax_n( q.k * SCALE ) * v[d][n]
__global__ void attn_kernel() {
    extern __shared__ float sm[];
    float* sQ = sm;                       // [BM][LDQ]  (rows = tokens, cols = d)
    float* sK = sQ + BM * LDQ;            // [BN][LDQ]
    float* sV = sK + BM * LDQ;            // [BN][LDQ]
    float* sS = sV + BM * LDQ;            // [BM][LDSS] probabilities

    int m0 = blockIdx.x * BM;
    int b = blockIdx.y;
    int s = blockIdx.z;
    const float* Q = &g_q[1 - s][b][0][0];
    const float* K = &g_k[s][b][0][0];
    const float* V = &g_v[s][b][0][0];

    int tid = threadIdx.x;
    int tx = tid & 15, ty = tid >> 4;     // tx: key/dim lanes, ty: query rows

    // load Q tile (transpose to token-major)
    for (int i = tid; i < HID * BM; i += 256) {
        int mrow = i & 63, d = i >> 6;
        sQ[mrow * LDQ + d] = Q[(size_t)d * NTOK + m0 + mrow];
    }

    float oacc[4][8] = {};                // [q local][dd], d = tx + 16*dd
    float mrun[4], lrun[4];
#pragma unroll
    for (int i = 0; i < 4; i++) { mrun[i] = -1e30f; lrun[i] = 0.f; }
    __syncthreads();

    for (int n0 = 0; n0 < NTOK; n0 += BN) {
        for (int i = tid; i < HID * BN; i += 256) {
            int nr = i & 63, d = i >> 6;
            size_t g = (size_t)d * NTOK + n0 + nr;
            sK[nr * LDQ + d] = K[g];
            sV[nr * LDQ + d] = V[g];
        }
        __syncthreads();

        // S = Q K^T  (q = ty*4+i, n = tx + 16*j)
        float sacc[4][4] = {};
#pragma unroll 4
        for (int d = 0; d < HID; d++) {
            float qr[4], kr[4];
#pragma unroll
            for (int i = 0; i < 4; i++) qr[i] = sQ[(ty * 4 + i) * LDQ + d];
#pragma unroll
            for (int j = 0; j < 4; j++) kr[j] = sK[(tx + 16 * j) * LDQ + d];
#pragma unroll
            for (int i = 0; i < 4; i++)
#pragma unroll
                for (int j = 0; j < 4; j++) sacc[i][j] += qr[i] * kr[j];
        }

        // online softmax per query row (row spread over the 16 tx lanes)
#pragma unroll
        for (int i = 0; i < 4; i++) {
            float mx = -1e30f;
#pragma unroll
            for (int j = 0; j < 4; j++) {
                sacc[i][j] *= ATT_SCALE;
                mx = fmaxf(mx, sacc[i][j]);
            }
#pragma unroll
            for (int off = 8; off >= 1; off >>= 1)
                mx = fmaxf(mx, __shfl_xor_sync(0xffffffffu, mx, off));
            float mnew = fmaxf(mrun[i], mx);
            float corr = __expf(mrun[i] - mnew);
            float psum = 0.f;
#pragma unroll
            for (int j = 0; j < 4; j++) {
                float p = __expf(sacc[i][j] - mnew);
                sS[(ty * 4 + i) * LDSS + tx + 16 * j] = p;
                psum += p;
            }
#pragma unroll
            for (int off = 8; off >= 1; off >>= 1)
                psum += __shfl_xor_sync(0xffffffffu, psum, off);
            lrun[i] = lrun[i] * corr + psum;
            mrun[i] = mnew;
#pragma unroll
            for (int dd = 0; dd < 8; dd++) oacc[i][dd] *= corr;
        }
        __syncwarp();   // sS rows are produced and consumed within the same warp

        // O += P V   (d = tx + 16*dd, conflict-free sV reads)
#pragma unroll 2
        for (int n = 0; n < BN; n++) {
            float vv[8];
#pragma unroll
            for (int dd = 0; dd < 8; dd++) vv[dd] = sV[n * LDQ + tx + 16 * dd];
#pragma unroll
            for (int i = 0; i < 4; i++) {
                float p = sS[(ty * 4 + i) * LDSS + n];
#pragma unroll
                for (int dd = 0; dd < 8; dd++) oacc[i][dd] += p * vv[dd];
            }
        }
        __syncthreads();   // before next tile overwrites sK/sV
    }

    // epilogue: normalize and write h[s][b][m][d]
#pragma unroll
    for (int i = 0; i < 4; i++) {
        float inv = 1.f / lrun[i];
        int m = m0 + ty * 4 + i;
        float* dst = &g_h[s][b][m][0];
#pragma unroll
        for (int dd = 0; dd < 8; dd++) dst[tx + 16 * dd] = oacc[i][dd] * inv;
    }
}

// ---------------- output projection + bias + residual ----------------
// o[b][o][m] = sum_c h[m][c] * w_eff[c][o] + bias[o] + x[b][o][m]
__global__ void out_kernel(const float* __restrict__ x0, const float* __restrict__ x1,
                           const float* __restrict__ ob0, const float* __restrict__ ob1,
                           float* __restrict__ out) {
    int z = blockIdx.z;
    int s = z / NB, b = z % NB;
    const float* x = (s == 0 ? x0 : x1) + (size_t)b * C_IN * NTOK;
    const float* ob = (s == 0 ? ob0 : ob1);
    float* o_out = out + (size_t)s * NB * C_IN * NTOK + (size_t)b * C_IN * NTOK;
    const float* H = &g_h[s][b][0][0];       // [NTOK][HID]
    const float* We = &g_weff[s][0][0];      // [HID][C_IN]

    int o0 = blockIdx.y * 64;
    int m0 = blockIdx.x * 64;
    __shared__ float sWe[16 * 64];           // [cc][oo]
    __shared__ float sH[16 * 65];            // [cc][mm], padded

    int tid = threadIdx.x;
    int tx = tid & 15, ty = tid >> 4;
    float acc[4][4] = {};

    for (int k0 = 0; k0 < HID; k0 += 16) {
        for (int i = tid; i < 16 * 64; i += 256) {
            int oo = i & 63, cc = i >> 6;
            sWe[cc * 64 + oo] = We[(size_t)(k0 + cc) * C_IN + o0 + oo];
        }
        for (int i = tid; i < 16 * 64; i += 256) {
            int cc = i & 15, mm = i >> 4;
            sH[cc * 65 + mm] = H[(size_t)(m0 + mm) * HID + k0 + cc];
        }
        __syncthreads();
#pragma unroll
        for (int kk = 0; kk < 16; kk++) {
            float wr[4], hr[4];
#pragma unroll
            for (int i = 0; i < 4; i++) wr[i] = sWe[kk * 64 + ty * 4 + i];
#pragma unroll
            for (int j = 0; j < 4; j++) hr[j] = sH[kk * 65 + tx + 16 * j];
#pragma unroll
            for (int i = 0; i < 4; i++)
#pragma unroll
                for (int j = 0; j < 4; j++) acc[i][j] += wr[i] * hr[j];
        }
        __syncthreads();
    }
#pragma unroll
    for (int i = 0; i < 4; i++) {
        int o = o0 + ty * 4 + i;
        float bv = ob[o];
#pragma unroll
        for (int j = 0; j < 4; j++) {
            int m = m0 + tx + 16 * j;
            size_t idx = (size_t)o * NTOK + m;
            o_out[idx] = acc[i][j] + bv + x[idx];
        }
    }
}

// ---------------- launch ----------------
extern "C" void kernel_launch(void* const* d_in, const int* in_sizes, int n_in,
                              void* d_out, int out_size) {
    const float* x0  = (const float*)d_in[0];
    const float* x1  = (const float*)d_in[1];
    const float* ew0 = (const float*)d_in[2];
    const float* eb0 = (const float*)d_in[3];
    const float* ew1 = (const float*)d_in[4];
    const float* eb1 = (const float*)d_in[5];
    const float* ow0 = (const float*)d_in[6];
    const float* ob0 = (const float*)d_in[7];
    const float* ow1 = (const float*)d_in[8];
    const float* ob1 = (const float*)d_in[9];
    float* out = (float*)d_out;

    dim3 ge(NTOK / 64, O3 / 64, NSTREAMS * NB);
    embed_kernel<<<ge, 256>>>(x0, x1, ew0, eb0, ew1, eb1);

    weff_kernel<<<dim3(HID, NSTREAMS), 256>>>(ow0, ow1);

    size_t smem = (size_t)(3 * BM * LDQ + BM * LDSS) * sizeof(float);
    cudaFuncSetAttribute(attn_kernel, cudaFuncAttributeMaxDynamicSharedMemorySize, (int)smem);
    attn_kernel<<<dim3(NTOK / BM, NB, NSTREAMS), 256, smem>>>();

    dim3 go(NTOK / 64, C_IN / 64, NSTREAMS * NB);
    out_kernel<<<go, 256>>>(x0, x1, ob0, ob1, out);
}

// round 4
// speedup vs baseline: 2.8383x; 2.8383x over previous
#include <cuda_runtime.h>
#include <cstdint>

#define NSTREAMS 2
#define NB 8
#define C_IN 256
#define HID 128
#define NTOK 2304
#define O3 384
#define QSCL 0.09016844005f   // 256^-0.5 * log2(e), folded into q at embed time

// ---------------- scratch (device globals; no allocs allowed) ----------------
__device__ float g_q[NSTREAMS][NB][NTOK][HID];   // token-major, pre-scaled+tf32-rounded
__device__ float g_k[NSTREAMS][NB][NTOK][HID];   // token-major, tf32-rounded
__device__ float g_v[NSTREAMS][NB][HID][NTOK];   // channel-major, tf32-rounded
__device__ float g_h[NSTREAMS][NB][NTOK][HID];   // attention output (fp32)
__device__ float g_weff[NSTREAMS][HID][C_IN];    // head-folded output weight

// ---------------- helpers ----------------
__device__ __forceinline__ float ex2f(float x) {
    float y; asm("ex2.approx.ftz.f32 %0, %1;" : "=f"(y) : "f"(x)); return y;
}
__device__ __forceinline__ float tf32r(float x) {
    uint32_t u; asm("cvt.rna.tf32.f32 %0, %1;" : "=r"(u) : "f"(x));
    return __uint_as_float(u);
}
__device__ __forceinline__ void mma8(float c[4], const uint32_t a[4],
                                     uint32_t b0, uint32_t b1) {
    asm volatile(
        "mma.sync.aligned.m16n8k8.row.col.f32.tf32.tf32.f32 "
        "{%0,%1,%2,%3}, {%4,%5,%6,%7}, {%8,%9}, {%0,%1,%2,%3};"
        : "+f"(c[0]), "+f"(c[1]), "+f"(c[2]), "+f"(c[3])
        : "r"(a[0]), "r"(a[1]), "r"(a[2]), "r"(a[3]), "r"(b0), "r"(b1));
}

// ---------------- embed: e = W x + b -> q/k/v (tf32-rounded) ----------------
__global__ void embed_kernel(const float* __restrict__ x0, const float* __restrict__ x1,
                             const float* __restrict__ w0, const float* __restrict__ b0,
                             const float* __restrict__ w1, const float* __restrict__ b1) {
    int z = blockIdx.z;
    int s = z / NB, b = z % NB;
    const float* x = (s == 0 ? x0 : x1) + (size_t)b * C_IN * NTOK;
    const float* w = (s == 0 ? w0 : w1);
    const float* bias = (s == 0 ? b0 : b1);
    int o0 = blockIdx.y * 64;
    int m0 = blockIdx.x * 64;

    __shared__ float sW[16 * 65];
    __shared__ float sX[16 * 64];
    __shared__ float sT[64 * 65];

    int tid = threadIdx.x;
    int tx = tid & 15, ty = tid >> 4;
    float acc[4][4] = {};

    for (int k0 = 0; k0 < C_IN; k0 += 16) {
        for (int i = tid; i < 64 * 16; i += 256) {
            int oo = i >> 4, cc = i & 15;
            sW[cc * 65 + oo] = w[(size_t)(o0 + oo) * C_IN + k0 + cc];
        }
        for (int i = tid; i < 16 * 64; i += 256) {
            int cc = i >> 6, mm = i & 63;
            sX[cc * 64 + mm] = x[(size_t)(k0 + cc) * NTOK + m0 + mm];
        }
        __syncthreads();
#pragma unroll
        for (int kk = 0; kk < 16; kk++) {
            float wr[4], xr[4];
#pragma unroll
            for (int i = 0; i < 4; i++) wr[i] = sW[kk * 65 + ty * 4 + i];
#pragma unroll
            for (int j = 0; j < 4; j++) xr[j] = sX[kk * 64 + tx + 16 * j];
#pragma unroll
            for (int i = 0; i < 4; i++)
#pragma unroll
                for (int j = 0; j < 4; j++) acc[i][j] += wr[i] * xr[j];
        }
        __syncthreads();
    }

    int y = blockIdx.y;
    if (y < 4) {
        // q (y<2) or k: transpose to token-major; fold QSCL into q; tf32 round
        float scl = (y < 2) ? QSCL : 1.0f;
#pragma unroll
        for (int i = 0; i < 4; i++) {
            float bv = bias[o0 + ty * 4 + i];
#pragma unroll
            for (int j = 0; j < 4; j++)
                sT[(tx + 16 * j) * 65 + ty * 4 + i] = tf32r((acc[i][j] + bv) * scl);
        }
        __syncthreads();
        float* base = (y < 2) ? &g_q[s][b][0][0] : &g_k[s][b][0][0];
        int ob = (y & 1) * 64;
        for (int idx = tid; idx < 4096; idx += 256) {
            int mm = idx >> 6, oo = idx & 63;
            base[(size_t)(m0 + mm) * HID + ob + oo] = sT[mm * 65 + oo];
        }
    } else {
        // v: channel-major, tf32-rounded
#pragma unroll
        for (int i = 0; i < 4; i++) {
            int c = o0 + ty * 4 + i - 2 * HID;
            float bv = bias[o0 + ty * 4 + i];
#pragma unroll
            for (int j = 0; j < 4; j++)
                g_v[s][b][c][m0 + tx + 16 * j] = tf32r(acc[i][j] + bv);
        }
    }
}

// ---------------- head-fold output weight ----------------
__global__ void weff_kernel(const float* __restrict__ w0, const float* __restrict__ w1) {
    int c = blockIdx.x, s = blockIdx.y;
    const float* w = (s == 0 ? w0 : w1);
    int o = threadIdx.x;
    float acc = 0.f;
#pragma unroll
    for (int j = 0; j < 4; j++) acc += w[(size_t)(c + HID * j) * C_IN + o];
    g_weff[s][c][o] = acc;
}

// ---------------- tf32 mma.sync flash attention ----------------
// SMEM fragment layouts (float index):
//   qf: ((w*16+ks)*4 + r)*32 + lane   value = Q[m0+16w+(l>>2)+8*(r&1)][8ks+(l&3)+4*(r>>1)]
//   kf: ((nt*16+ks)*2 + r)*32 + lane  value = K[n0+8nt+(l>>2)][8ks+(l&3)+4r]
//   vf: ((dt*16+k2)*2 + r)*32 + lane  value = V[8dt+(l>>2)][n0+8k2+(l&3)+4r]
__global__ void __launch_bounds__(256, 1) attn_kernel() {
    extern __shared__ float sf[];
    float* qf = sf;              // 16384 floats
    float* kf = sf + 16384;      // 16384
    float* vf = sf + 32768;      // 16384

    int tid = threadIdx.x;
    int l = tid & 31, w = tid >> 5;
    int m0 = blockIdx.x * 128;
    int b = blockIdx.y, s = blockIdx.z;
    const float* Q = &g_q[1 - s][b][0][0];
    const float* K = &g_k[s][b][0][0];
    const float* V = &g_v[s][b][0][0];

    // stage Q fragments (once)
    for (int i = tid; i < 4096; i += 256) {
        int q = i >> 5, c4 = i & 31;
        float4 v4 = *(const float4*)(Q + (size_t)(m0 + q) * HID + c4 * 4);
        int wq = q >> 4, rlo = (q >> 3) & 1, g = q & 7;
        int ks = c4 >> 1, rhi = c4 & 1;
        *(float4*)(qf + (((wq * 16 + ks) * 4 + (rlo + 2 * rhi)) * 32 + 4 * g)) = v4;
    }

    float oacc[16][4];
#pragma unroll
    for (int dt = 0; dt < 16; dt++)
#pragma unroll
        for (int r = 0; r < 4; r++) oacc[dt][r] = 0.f;
    float psum0 = 0.f, psum1 = 0.f;

    for (int it = 0; it < 18; it++) {
        int n0 = it * 128;
        __syncthreads();   // prev-iter readers of kf/vf done (also covers qf staging)

        // stage K and V tiles into fragment order
        for (int i = tid; i < 4096; i += 256) {
            int row = i >> 5, c4 = i & 31;
            float4 kv = *(const float4*)(K + (size_t)(n0 + row) * HID + c4 * 4);
            int nt = row >> 3, g = row & 7, ks = c4 >> 1, r = c4 & 1;
            *(float4*)(kf + (((nt * 16 + ks) * 2 + r) * 32 + 4 * g)) = kv;
            float4 vv = *(const float4*)(V + (size_t)row * NTOK + n0 + c4 * 4);
            *(float4*)(vf + (((nt * 16 + ks) * 2 + r) * 32 + 4 * g)) = vv;  // dt=nt,k2=ks roles
        }
        __syncthreads();

        // ---- S = Q K^T (16q x 128keys per warp) ----
        float sacc[16][4];
#pragma unroll
        for (int nt = 0; nt < 16; nt++)
#pragma unroll
            for (int r = 0; r < 4; r++) sacc[nt][r] = 0.f;

#pragma unroll 4
        for (int ks = 0; ks < 16; ks++) {
            uint32_t a[4];
            const float* qb = qf + (w * 16 + ks) * 128 + l;
#pragma unroll
            for (int r = 0; r < 4; r++) a[r] = __float_as_uint(qb[r * 32]);
#pragma unroll
            for (int nt = 0; nt < 16; nt++) {
                const float* kb = kf + (nt * 16 + ks) * 64 + l;
                mma8(sacc[nt], a, __float_as_uint(kb[0]), __float_as_uint(kb[32]));
            }
        }

        // ---- softmax: P = exp2(S) (scale folded into q), accumulate row sums ----
#pragma unroll
        for (int nt = 0; nt < 16; nt++) {
            float p0 = ex2f(sacc[nt][0]);
            float p1 = ex2f(sacc[nt][1]);
            float p2 = ex2f(sacc[nt][2]);
            float p3 = ex2f(sacc[nt][3]);
            psum0 += p0 + p1;
            psum1 += p2 + p3;
            sacc[nt][0] = tf32r(p0);
            sacc[nt][1] = tf32r(p1);
            sacc[nt][2] = tf32r(p2);
            sacc[nt][3] = tf32r(p3);
        }

        // ---- O += P V ----
        int j = l & 3;
        int s0 = (l & ~3) | (j >> 1);
        int s1 = s0 + 2;
        bool odd = (j & 1) != 0;
#pragma unroll
        for (int k2 = 0; k2 < 16; k2++) {
            uint32_t c0 = __float_as_uint(sacc[k2][0]);
            uint32_t c1 = __float_as_uint(sacc[k2][1]);
            uint32_t c2 = __float_as_uint(sacc[k2][2]);
            uint32_t c3 = __float_as_uint(sacc[k2][3]);
            uint32_t t00 = __shfl_sync(0xffffffffu, c0, s0);
            uint32_t t01 = __shfl_sync(0xffffffffu, c1, s0);
            uint32_t t20 = __shfl_sync(0xffffffffu, c0, s1);
            uint32_t t21 = __shfl_sync(0xffffffffu, c1, s1);
            uint32_t t10 = __shfl_sync(0xffffffffu, c2, s0);
            uint32_t t11 = __shfl_sync(0xffffffffu, c3, s0);
            uint32_t t30 = __shfl_sync(0xffffffffu, c2, s1);
            uint32_t t31 = __shfl_sync(0xffffffffu, c3, s1);
            uint32_t apv[4];
            apv[0] = odd ? t01 : t00;
            apv[2] = odd ? t21 : t20;
            apv[1] = odd ? t11 : t10;
            apv[3] = odd ? t31 : t30;
#pragma unroll
            for (int dt = 0; dt < 16; dt++) {
                const float* vb = vf + (dt * 16 + k2) * 64 + l;
                mma8(oacc[dt], apv, __float_as_uint(vb[0]), __float_as_uint(vb[32]));
            }
        }
    }

    // ---- epilogue: normalize rows, write h ----
    psum0 += __shfl_xor_sync(0xffffffffu, psum0, 1);
    psum0 += __shfl_xor_sync(0xffffffffu, psum0, 2);
    psum1 += __shfl_xor_sync(0xffffffffu, psum1, 1);
    psum1 += __shfl_xor_sync(0xffffffffu, psum1, 2);
    float inv0 = 1.f / psum0, inv1 = 1.f / psum1;

    int g = l >> 2, j = l & 3;
    int q0 = m0 + 16 * w + g;
    float* h0 = &g_h[s][b][q0][0];
    float* h1 = &g_h[s][b][q0 + 8][0];
#pragma unroll
    for (int dt = 0; dt < 16; dt++) {
        float2 e0 = make_float2(oacc[dt][0] * inv0, oacc[dt][1] * inv0);
        float2 e1 = make_float2(oacc[dt][2] * inv1, oacc[dt][3] * inv1);
        *(float2*)(h0 + 8 * dt + 2 * j) = e0;
        *(float2*)(h1 + 8 * dt + 2 * j) = e1;
    }
}

// ---------------- output projection + bias + residual ----------------
__global__ void out_kernel(const float* __restrict__ x0, const float* __restrict__ x1,
                           const float* __restrict__ ob0, const float* __restrict__ ob1,
                           float* __restrict__ out) {
    int z = blockIdx.z;
    int s = z / NB, b = z % NB;
    const float* x = (s == 0 ? x0 : x1) + (size_t)b * C_IN * NTOK;
    const float* ob = (s == 0 ? ob0 : ob1);
    float* o_out = out + (size_t)s * NB * C_IN * NTOK + (size_t)b * C_IN * NTOK;
    const float* H = &g_h[s][b][0][0];
    const float* We = &g_weff[s][0][0];

    int o0 = blockIdx.y * 64;
    int m0 = blockIdx.x * 64;
    __shared__ float sWe[16 * 64];
    __shared__ float sH[16 * 65];

    int tid = threadIdx.x;
    int tx = tid & 15, ty = tid >> 4;
    float acc[4][4] = {};

    for (int k0 = 0; k0 < HID; k0 += 16) {
        for (int i = tid; i < 16 * 64; i += 256) {
            int oo = i & 63, cc = i >> 6;
            sWe[cc * 64 + oo] = We[(size_t)(k0 + cc) * C_IN + o0 + oo];
        }
        for (int i = tid; i < 16 * 64; i += 256) {
            int cc = i & 15, mm = i >> 4;
            sH[cc * 65 + mm] = H[(size_t)(m0 + mm) * HID + k0 + cc];
        }
        __syncthreads();
#pragma unroll
        for (int kk = 0; kk < 16; kk++) {
            float wr[4], hr[4];
#pragma unroll
            for (int i = 0; i < 4; i++) wr[i] = sWe[kk * 64 + ty * 4 + i];
#pragma unroll
            for (int j = 0; j < 4; j++) hr[j] = sH[kk * 65 + tx + 16 * j];
#pragma unroll
            for (int i = 0; i < 4; i++)
#pragma unroll
                for (int j = 0; j < 4; j++) acc[i][j] += wr[i] * hr[j];
        }
        __syncthreads();
    }
#pragma unroll
    for (int i = 0; i < 4; i++) {
        int o = o0 + ty * 4 + i;
        float bv = ob[o];
#pragma unroll
        for (int j = 0; j < 4; j++) {
            int m = m0 + tx + 16 * j;
            size_t idx = (size_t)o * NTOK + m;
            o_out[idx] = acc[i][j] + bv + x[idx];
        }
    }
}

// ---------------- launch ----------------
extern "C" void kernel_launch(void* const* d_in, const int* in_sizes, int n_in,
                              void* d_out, int out_size) {
    const float* x0  = (const float*)d_in[0];
    const float* x1  = (const float*)d_in[1];
    const float* ew0 = (const float*)d_in[2];
    const float* eb0 = (const float*)d_in[3];
    const float* ew1 = (const float*)d_in[4];
    const float* eb1 = (const float*)d_in[5];
    const float* ow0 = (const float*)d_in[6];
    const float* ob0 = (const float*)d_in[7];
    const float* ow1 = (const float*)d_in[8];
    const float* ob1 = (const float*)d_in[9];
    float* out = (float*)d_out;

    dim3 ge(NTOK / 64, O3 / 64, NSTREAMS * NB);
    embed_kernel<<<ge, 256>>>(x0, x1, ew0, eb0, ew1, eb1);

    weff_kernel<<<dim3(HID, NSTREAMS), 256>>>(ow0, ow1);

    int smem = 3 * 16384 * 4;   // 192 KB
    cudaFuncSetAttribute(attn_kernel, cudaFuncAttributeMaxDynamicSharedMemorySize, smem);
    attn_kernel<<<dim3(NTOK / 128, NB, NSTREAMS), 256, smem>>>();

    dim3 go(NTOK / 64, C_IN / 64, NSTREAMS * NB);
    out_kernel<<<go, 256>>>(x0, x1, ob0, ob1, out);
}

// round 6
// speedup vs baseline: 4.4076x; 1.5529x over previous
#include <cuda_runtime.h>
#include <cstdint>

#define NSTREAMS 2
#define NB 8
#define C_IN 256
#define HID 128
#define NTOK 2304
#define QSCL 0.09016844005f   // 256^-0.5 * log2(e), folded into q at embed time

// ---------------- scratch (device globals; no allocs allowed) ----------------
__device__ float g_q[NSTREAMS][NB][NTOK][HID];   // token-major, scaled + tf32
__device__ float g_k[NSTREAMS][NB][NTOK][HID];   // token-major, tf32
__device__ float g_v[NSTREAMS][NB][HID][NTOK];   // channel-major, tf32
__device__ float g_h[NSTREAMS][NB][NTOK][HID];   // attn output, tf32
__device__ float g_wefft[NSTREAMS][C_IN][HID];   // head-folded out weight, [o][c], tf32

// ---------------- helpers ----------------
__device__ __forceinline__ float ex2f(float x) {
    float y; asm("ex2.approx.ftz.f32 %0, %1;" : "=f"(y) : "f"(x)); return y;
}
__device__ __forceinline__ float tf32r(float x) {
    uint32_t u; asm("cvt.rna.tf32.f32 %0, %1;" : "=r"(u) : "f"(x));
    return __uint_as_float(u);
}
__device__ __forceinline__ void mma8(float c[4], const uint32_t a[4],
                                     uint32_t b0, uint32_t b1) {
    asm volatile(
        "mma.sync.aligned.m16n8k8.row.col.f32.tf32.tf32.f32 "
        "{%0,%1,%2,%3}, {%4,%5,%6,%7}, {%8,%9}, {%0,%1,%2,%3};"
        : "+f"(c[0]), "+f"(c[1]), "+f"(c[2]), "+f"(c[3])
        : "r"(a[0]), "r"(a[1]), "r"(a[2]), "r"(a[3]), "r"(b0), "r"(b1));
}
__device__ __forceinline__ uint32_t smem_u32(const void* p) {
    uint32_t a;
    asm("{ .reg .u64 t; cvta.to.shared.u64 t, %1; cvt.u32.u64 %0, t; }" : "=r"(a) : "l"(p));
    return a;
}
#define CP16(dst, src) asm volatile("cp.async.cg.shared.global [%0], [%1], 16;" :: "r"(dst), "l"(src))
#define CP_COMMIT()    asm volatile("cp.async.commit_group;" ::: "memory")
#define CP_WAIT1()     asm volatile("cp.async.wait_group 1;" ::: "memory")
#define CP_WAIT0()     asm volatile("cp.async.wait_group 0;" ::: "memory")

// =======================================================================
// embed (tf32 mma): E[o][m] = sum_c W[o][c] X[c][m];  o-tile selects q/k/v
// CTA: 128o x 128m, 8 warps (warp = 16o x 128m), K chunks of 64
// =======================================================================
__global__ void __launch_bounds__(256, 2) embed_kernel(
        const float* __restrict__ x0, const float* __restrict__ x1,
        const float* __restrict__ w0, const float* __restrict__ b0,
        const float* __restrict__ w1, const float* __restrict__ b1) {
    extern __shared__ float sm[];
    float* sW = sm;           // [128][68]
    float* sX = sm + 8704;    // [64][132]

    int z = blockIdx.z;
    int s = z >> 3, b = z & 7;
    const float* x = (s == 0 ? x0 : x1) + (size_t)b * C_IN * NTOK;
    const float* w = (s == 0 ? w0 : w1);
    const float* bias = (s == 0 ? b0 : b1);
    int oy = blockIdx.y, o0 = oy * 128;
    int m0 = blockIdx.x * 128;

    int tid = threadIdx.x;
    int l = tid & 31, wq = tid >> 5;
    int g = l >> 2, j = l & 3;

    float acc[16][4] = {};

    for (int k0 = 0; k0 < C_IN; k0 += 64) {
        for (int u = tid; u < 2048; u += 256) {          // W: 128 rows x 16 f4
            int row = u >> 4, c4 = u & 15;
            float4 t = *(const float4*)(w + (size_t)(o0 + row) * C_IN + k0 + c4 * 4);
            t.x = tf32r(t.x); t.y = tf32r(t.y); t.z = tf32r(t.z); t.w = tf32r(t.w);
            *(float4*)(sW + row * 68 + c4 * 4) = t;
        }
        for (int u = tid; u < 2048; u += 256) {          // X: 64 rows x 32 f4
            int row = u >> 5, m4 = u & 31;
            float4 t = *(const float4*)(x + (size_t)(k0 + row) * NTOK + m0 + m4 * 4);
            t.x = tf32r(t.x); t.y = tf32r(t.y); t.z = tf32r(t.z); t.w = tf32r(t.w);
            *(float4*)(sX + row * 132 + m4 * 4) = t;
        }
        __syncthreads();
#pragma unroll
        for (int ks = 0; ks < 8; ks++) {
            uint32_t a[4];
            const float* wb = sW + (16 * wq + g) * 68 + 8 * ks + j;
            a[0] = __float_as_uint(wb[0]);
            a[1] = __float_as_uint(wb[8 * 68]);
            a[2] = __float_as_uint(wb[4]);
            a[3] = __float_as_uint(wb[8 * 68 + 4]);
            const float* xb0 = sX + (8 * ks + j) * 132 + g;
            const float* xb1 = xb0 + 4 * 132;
#pragma unroll
            for (int nt = 0; nt < 16; nt++)
                mma8(acc[nt], a, __float_as_uint(xb0[8 * nt]), __float_as_uint(xb1[8 * nt]));
        }
        __syncthreads();
    }

    if (oy == 2) {
        // v: channel-major direct (float2 along m)
        int d0 = 16 * wq + g, d1 = d0 + 8;
        float bv0 = bias[256 + d0], bv1 = bias[256 + d1];
        float* v0 = &g_v[s][b][d0][0];
        float* v1 = &g_v[s][b][d1][0];
#pragma unroll
        for (int nt = 0; nt < 16; nt++) {
            int m = m0 + 8 * nt + 2 * j;
            *(float2*)(v0 + m) = make_float2(tf32r(acc[nt][0] + bv0), tf32r(acc[nt][1] + bv0));
            *(float2*)(v1 + m) = make_float2(tf32r(acc[nt][2] + bv1), tf32r(acc[nt][3] + bv1));
        }
    } else {
        // q/k: transpose via SMEM to token-major
        float* sT = sm;   // [128 d][129 m]
        int d0 = 16 * wq + g, d1 = d0 + 8;
#pragma unroll
        for (int nt = 0; nt < 16; nt++) {
            int m = 8 * nt + 2 * j;
            sT[d0 * 129 + m]     = acc[nt][0];
            sT[d0 * 129 + m + 1] = acc[nt][1];
            sT[d1 * 129 + m]     = acc[nt][2];
            sT[d1 * 129 + m + 1] = acc[nt][3];
        }
        __syncthreads();
        float scl = (oy == 0) ? QSCL : 1.0f;
        float* base = (oy == 0) ? &g_q[s][b][0][0] : &g_k[s][b][0][0];
        float bv[4];
#pragma unroll
        for (int k = 0; k < 4; k++) bv[k] = bias[o0 + l + 32 * k];
        for (int mrow = wq; mrow < 128; mrow += 8) {
            float* dst = base + (size_t)(m0 + mrow) * HID;
#pragma unroll
            for (int k = 0; k < 4; k++) {
                int d = l + 32 * k;
                dst[d] = tf32r((sT[d * 129 + mrow] + bv[k]) * scl);
            }
        }
    }
}

// ---------------- head-fold + transpose output weight: [512,256] -> [256 o][128 c]
__global__ void weff_kernel(const float* __restrict__ w0, const float* __restrict__ w1) {
    int o = blockIdx.x, s = blockIdx.y;
    const float* w = (s == 0 ? w0 : w1);
    int c = threadIdx.x;   // 0..127
    float acc = 0.f;
#pragma unroll
    for (int k = 0; k < 4; k++) acc += w[(size_t)(c + HID * k) * C_IN + o];
    g_wefft[s][o][c] = tf32r(acc);
}

// =======================================================================
// attention: tf32 mma, 64-key sub-tiles, cp.async double buffer,
// swizzled fragment SMEM (lane4 ^= idx&7), Q fragments in registers
// =======================================================================
__global__ void __launch_bounds__(256, 1) attn_kernel() {
    extern __shared__ float sf[];
    float* buf0 = sf;            // 16384 floats (kf 8192 + vf 8192)
    float* buf1 = sf + 16384;

    int tid = threadIdx.x;
    int l = tid & 31, w = tid >> 5;
    int m0 = blockIdx.x * 128;
    int b = blockIdx.y, s = blockIdx.z;
    const float* Q = &g_q[1 - s][b][0][0];
    const float* K = &g_k[s][b][0][0];
    const float* V = &g_v[s][b][0][0];

    // ---- stage Q fragments into buf0, load to registers ----
    for (int i = tid; i < 4096; i += 256) {
        int q = i >> 5, c4 = i & 31;
        float4 v4 = *(const float4*)(Q + (size_t)(m0 + q) * HID + c4 * 4);
        int wq = q >> 4, rlo = (q >> 3) & 1, gq = q & 7;
        int ks = c4 >> 1, rhi = c4 & 1;
        int idxq = (wq * 16 + ks) * 4 + rlo + 2 * rhi;
        *(float4*)(buf0 + idxq * 32 + 4 * (gq ^ (idxq & 7))) = v4;
    }
    __syncthreads();
    uint32_t aq[16][4];
#pragma unroll
    for (int ks = 0; ks < 16; ks++)
#pragma unroll
        for (int r = 0; r < 4; r++) {
            int idxq = (w * 16 + ks) * 4 + r;
            aq[ks][r] = __float_as_uint(buf0[idxq * 32 + 4 * ((l >> 2) ^ (idxq & 7)) + (l & 3)]);
        }
    __syncthreads();

    // ---- per-thread cp.async source/dest precompute ----
    uint32_t sb0 = smem_u32(buf0), sb1 = smem_u32(buf1);
    uint32_t kdst[8], vdst[8];
    const char* ksrc[8];
    const char* vsrc[8];
#pragma unroll
    for (int u = 0; u < 8; u++) {
        // K: row = w + 8u (64 rows), c4 = l (32 f4 of d)
        kdst[u] = ((u * 16 + (l >> 1)) * 2 + (l & 1)) * 128 + 16 * (w ^ (l & 7));
        ksrc[u] = (const char*)(K + (size_t)(w + 8 * u) * HID + l * 4);
        // V: row = 2w + (l>>4) + 16u (128 d rows), k4 = l & 15
        int row = 2 * w + (l >> 4) + 16 * u;
        int k4 = l & 15;
        vdst[u] = 8192 * 4 + ((row >> 3) * 16 + k4) * 128 + 16 * ((row & 7) ^ (k4 & 7));
        vsrc[u] = (const char*)(V + (size_t)row * NTOK + k4 * 4);
    }

    // prefetch sub-tile 0 into buf0
#pragma unroll
    for (int u = 0; u < 8; u++) CP16(sb0 + kdst[u], ksrc[u]);
#pragma unroll
    for (int u = 0; u < 8; u++) CP16(sb0 + vdst[u], vsrc[u]);
    CP_COMMIT();

    float oacc[16][4] = {};
    float psum0 = 0.f, psum1 = 0.f;

    for (int t = 0; t < 36; t++) {
        const float* cb = (t & 1) ? buf1 : buf0;
        if (t + 1 < 36) {
            uint32_t nb = (t & 1) ? sb0 : sb1;
            size_t koff = (size_t)(t + 1) * 64 * HID * 4;
            size_t voff = (size_t)(t + 1) * 64 * 4;
#pragma unroll
            for (int u = 0; u < 8; u++) CP16(nb + kdst[u], ksrc[u] + koff);
#pragma unroll
            for (int u = 0; u < 8; u++) CP16(nb + vdst[u], vsrc[u] + voff);
            CP_COMMIT();
            CP_WAIT1();
        } else {
            CP_WAIT0();
        }
        __syncthreads();

        const float* kf = cb;
        const float* vf = cb + 8192;

        // ---- S = Q K^T : 16q x 64 keys per warp ----
        float sacc[8][4] = {};
#pragma unroll
        for (int ks = 0; ks < 16; ks++) {
            const float* kb = kf + ks * 64;
            int e0 = 4 * ((l >> 2) ^ ((2 * ks) & 7)) + (l & 3);
            int e1 = 4 * ((l >> 2) ^ ((2 * ks + 1) & 7)) + (l & 3);
#pragma unroll
            for (int nt = 0; nt < 8; nt++)
                mma8(sacc[nt], aq[ks],
                     __float_as_uint(kb[nt * 1024 + e0]),
                     __float_as_uint(kb[nt * 1024 + 32 + e1]));
        }

        // ---- softmax: P = exp2(S) (scale folded into q) ----
#pragma unroll
        for (int nt = 0; nt < 8; nt++) {
            float p0 = ex2f(sacc[nt][0]);
            float p1 = ex2f(sacc[nt][1]);
            float p2 = ex2f(sacc[nt][2]);
            float p3 = ex2f(sacc[nt][3]);
            psum0 += p0 + p1;
            psum1 += p2 + p3;
            sacc[nt][0] = tf32r(p0); sacc[nt][1] = tf32r(p1);
            sacc[nt][2] = tf32r(p2); sacc[nt][3] = tf32r(p3);
        }

        // ---- O += P V ----
        int jj = l & 3;
        int s0 = (l & ~3) | (jj >> 1);
        int s1 = s0 + 2;
        bool odd = (jj & 1) != 0;
#pragma unroll
        for (int k2 = 0; k2 < 8; k2++) {
            uint32_t c0 = __float_as_uint(sacc[k2][0]);
            uint32_t c1 = __float_as_uint(sacc[k2][1]);
            uint32_t c2 = __float_as_uint(sacc[k2][2]);
            uint32_t c3 = __float_as_uint(sacc[k2][3]);
            uint32_t t00 = __shfl_sync(0xffffffffu, c0, s0);
            uint32_t t01 = __shfl_sync(0xffffffffu, c1, s0);
            uint32_t t20 = __shfl_sync(0xffffffffu, c0, s1);
            uint32_t t21 = __shfl_sync(0xffffffffu, c1, s1);
            uint32_t t10 = __shfl_sync(0xffffffffu, c2, s0);
            uint32_t t11 = __shfl_sync(0xffffffffu, c3, s0);
            uint32_t t30 = __shfl_sync(0xffffffffu, c2, s1);
            uint32_t t31 = __shfl_sync(0xffffffffu, c3, s1);
            uint32_t apv[4];
            apv[0] = odd ? t01 : t00;
            apv[2] = odd ? t21 : t20;
            apv[1] = odd ? t11 : t10;
            apv[3] = odd ? t31 : t30;
            const float* vb = vf + k2 * 64;
            int e0 = 4 * ((l >> 2) ^ ((2 * k2) & 7)) + (l & 3);
            int e1 = 4 * ((l >> 2) ^ ((2 * k2 + 1) & 7)) + (l & 3);
#pragma unroll
            for (int dt = 0; dt < 16; dt++)
                mma8(oacc[dt], apv,
                     __float_as_uint(vb[dt * 512 + e0]),
                     __float_as_uint(vb[dt * 512 + 32 + e1]));
        }
        __syncthreads();
    }

    // ---- epilogue: normalize rows, tf32-round, write h ----
    psum0 += __shfl_xor_sync(0xffffffffu, psum0, 1);
    psum0 += __shfl_xor_sync(0xffffffffu, psum0, 2);
    psum1 += __shfl_xor_sync(0xffffffffu, psum1, 1);
    psum1 += __shfl_xor_sync(0xffffffffu, psum1, 2);
    float inv0 = 1.f / psum0, inv1 = 1.f / psum1;

    int g = l >> 2, j = l & 3;
    int q0 = m0 + 16 * w + g;
    float* h0 = &g_h[s][b][q0][0];
    float* h1 = &g_h[s][b][q0 + 8][0];
#pragma unroll
    for (int dt = 0; dt < 16; dt++) {
        *(float2*)(h0 + 8 * dt + 2 * j) =
            make_float2(tf32r(oacc[dt][0] * inv0), tf32r(oacc[dt][1] * inv0));
        *(float2*)(h1 + 8 * dt + 2 * j) =
            make_float2(tf32r(oacc[dt][2] * inv1), tf32r(oacc[dt][3] * inv1));
    }
}

// =======================================================================
// out (tf32 mma): out[o][m] = sum_c Wt[o][c] H[m][c] + bias[o] + x[o][m]
// CTA: 128o x 128m, K = 128 in 2 chunks of 64
// =======================================================================
__global__ void __launch_bounds__(256, 2) out_kernel(
        const float* __restrict__ x0, const float* __restrict__ x1,
        const float* __restrict__ ob0, const float* __restrict__ ob1,
        float* __restrict__ out) {
    extern __shared__ float sm[];
    float* sWe = sm;          // [128][68]
    float* sH  = sm + 8704;   // [128][68]

    int z = blockIdx.z;
    int s = z >> 3, b = z & 7;
    const float* x = (s == 0 ? x0 : x1) + (size_t)b * C_IN * NTOK;
    const float* ob = (s == 0 ? ob0 : ob1);
    float* o_out = out + (size_t)s * NB * C_IN * NTOK + (size_t)b * C_IN * NTOK;
    int ot = blockIdx.y;
    int m0 = blockIdx.x * 128;
    const float* Wt = &g_wefft[s][ot * 128][0];
    const float* H = &g_h[s][b][0][0];

    int tid = threadIdx.x;
    int l = tid & 31, wq = tid >> 5;
    int g = l >> 2, j = l & 3;

    float acc[16][4] = {};

    for (int c0 = 0; c0 < HID; c0 += 64) {
        for (int u = tid; u < 2048; u += 256) {   // Wt: 128 rows x 16 f4
            int row = u >> 4, c4 = u & 15;
            *(float4*)(sWe + row * 68 + c4 * 4) =
                *(const float4*)(Wt + (size_t)row * HID + c0 + c4 * 4);
        }
        for (int u = tid; u < 2048; u += 256) {   // H: 128 rows x 16 f4
            int row = u >> 4, c4 = u & 15;
            *(float4*)(sH + row * 68 + c4 * 4) =
                *(const float4*)(H + (size_t)(m0 + row) * HID + c0 + c4 * 4);
        }
        __syncthreads();
#pragma unroll
        for (int ks = 0; ks < 8; ks++) {
            uint32_t a[4];
            const float* wb = sWe + (16 * wq + g) * 68 + 8 * ks + j;
            a[0] = __float_as_uint(wb[0]);
            a[1] = __float_as_uint(wb[8 * 68]);
            a[2] = __float_as_uint(wb[4]);
            a[3] = __float_as_uint(wb[8 * 68 + 4]);
            const float* hb0 = sH + g * 68 + 8 * ks + j;
            const float* hb1 = hb0 + 4;
#pragma unroll
            for (int nt = 0; nt < 16; nt++)
                mma8(acc[nt], a,
                     __float_as_uint(hb0[nt * 8 * 68]),
                     __float_as_uint(hb1[nt * 8 * 68]));
        }
        __syncthreads();
    }

    int o_a = ot * 128 + 16 * wq + g, o_b = o_a + 8;
    float bva = ob[o_a], bvb = ob[o_b];
#pragma unroll
    for (int nt = 0; nt < 16; nt++) {
        int m = m0 + 8 * nt + 2 * j;
        size_t ia = (size_t)o_a * NTOK + m;
        size_t ib = (size_t)o_b * NTOK + m;
        float2 xa = *(const float2*)(x + ia);
        float2 xb = *(const float2*)(x + ib);
        *(float2*)(o_out + ia) = make_float2(acc[nt][0] + bva + xa.x, acc[nt][1] + bva + xa.y);
        *(float2*)(o_out + ib) = make_float2(acc[nt][2] + bvb + xb.x, acc[nt][3] + bvb + xb.y);
    }
}

// ---------------- launch ----------------
extern "C" void kernel_launch(void* const* d_in, const int* in_sizes, int n_in,
                              void* d_out, int out_size) {
    const float* x0  = (const float*)d_in[0];
    const float* x1  = (const float*)d_in[1];
    const float* ew0 = (const float*)d_in[2];
    const float* eb0 = (const float*)d_in[3];
    const float* ew1 = (const float*)d_in[4];
    const float* eb1 = (const float*)d_in[5];
    const float* ow0 = (const float*)d_in[6];
    const float* ob0 = (const float*)d_in[7];
    const float* ow1 = (const float*)d_in[8];
    const float* ob1 = (const float*)d_in[9];
    float* out = (float*)d_out;

    int smem_e = 17152 * 4;
    cudaFuncSetAttribute(embed_kernel, cudaFuncAttributeMaxDynamicSharedMemorySize, smem_e);
    embed_kernel<<<dim3(NTOK / 128, 3, 16), 256, smem_e>>>(x0, x1, ew0, eb0, ew1, eb1);

    weff_kernel<<<dim3(C_IN, NSTREAMS), HID>>>(ow0, ow1);

    int smem_a = 32768 * 4;
    cudaFuncSetAttribute(attn_kernel, cudaFuncAttributeMaxDynamicSharedMemorySize, smem_a);
    attn_kernel<<<dim3(NTOK / 128, NB, NSTREAMS), 256, smem_a>>>();

    int smem_o = 17408 * 4;
    cudaFuncSetAttribute(out_kernel, cudaFuncAttributeMaxDynamicSharedMemorySize, smem_o);
    out_kernel<<<dim3(NTOK / 128, 2, 16), 256, smem_o>>>(x0, x1, ob0, ob1, out);
}

// round 10
// speedup vs baseline: 9.3329x; 2.1175x over previous
#include <cuda_runtime.h>
#include <cuda_fp16.h>
#include <cstdint>

#define NSTREAMS 2
#define NB 8
#define C_IN 256
#define HID 128
#define NTOK 2304
#define QSCL 0.09016844005f   // 256^-0.5 * log2(e), folded into q at embed time

// ---------------- scratch (device globals; no allocs allowed) ----------------
__device__ __half g_qh[NSTREAMS][NB][NTOK][HID];  // token-major, scaled, fp16
__device__ __half g_kh[NSTREAMS][NB][NTOK][HID];  // token-major, fp16
__device__ __half g_vh[NSTREAMS][NB][HID][NTOK];  // channel-major, fp16
__device__ float  g_h[NSTREAMS][NB][NTOK][HID];   // attn output, tf32-rounded fp32
__device__ float  g_wefft[NSTREAMS][C_IN][HID];   // head-folded out weight [o][c], tf32

// ---------------- helpers ----------------
__device__ __forceinline__ float ex2f(float x) {
    float y; asm("ex2.approx.ftz.f32 %0, %1;" : "=f"(y) : "f"(x)); return y;
}
__device__ __forceinline__ float tf32r(float x) {
    uint32_t u; asm("cvt.rna.tf32.f32 %0, %1;" : "=r"(u) : "f"(x));
    return __uint_as_float(u);
}
__device__ __forceinline__ uint32_t packh(float lo, float hi) {
    uint32_t d; asm("cvt.rn.f16x2.f32 %0, %1, %2;" : "=r"(d) : "f"(hi), "f"(lo));
    return d;
}
__device__ __forceinline__ void mma8(float c[4], const uint32_t a[4],
                                     uint32_t b0, uint32_t b1) {
    asm volatile(
        "mma.sync.aligned.m16n8k8.row.col.f32.tf32.tf32.f32 "
        "{%0,%1,%2,%3}, {%4,%5,%6,%7}, {%8,%9}, {%0,%1,%2,%3};"
        : "+f"(c[0]), "+f"(c[1]), "+f"(c[2]), "+f"(c[3])
        : "r"(a[0]), "r"(a[1]), "r"(a[2]), "r"(a[3]), "r"(b0), "r"(b1));
}
__device__ __forceinline__ void mma16(float c[4], const uint32_t a[4],
                                      uint32_t b0, uint32_t b1) {
    asm volatile(
        "mma.sync.aligned.m16n8k16.row.col.f32.f16.f16.f32 "
        "{%0,%1,%2,%3}, {%4,%5,%6,%7}, {%8,%9}, {%0,%1,%2,%3};"
        : "+f"(c[0]), "+f"(c[1]), "+f"(c[2]), "+f"(c[3])
        : "r"(a[0]), "r"(a[1]), "r"(a[2]), "r"(a[3]), "r"(b0), "r"(b1));
}
__device__ __forceinline__ uint32_t smem_u32(const void* p) {
    uint32_t a;
    asm("{ .reg .u64 t; cvta.to.shared.u64 t, %1; cvt.u32.u64 %0, t; }" : "=r"(a) : "l"(p));
    return a;
}
#define CP16(dst, src) asm volatile("cp.async.cg.shared.global [%0], [%1], 16;" :: "r"(dst), "l"(src))
#define CP_COMMIT()    asm volatile("cp.async.commit_group;" ::: "memory")
#define CP_WAIT1()     asm volatile("cp.async.wait_group 1;" ::: "memory")
#define CP_WAIT0()     asm volatile("cp.async.wait_group 0;" ::: "memory")

// =======================================================================
// embed (tf32 mma): E[o][m] = sum_c W[o][c] X[c][m];  o-tile selects q/k/v
// =======================================================================
__global__ void __launch_bounds__(256, 2) embed_kernel(
        const float* __restrict__ x0, const float* __restrict__ x1,
        const float* __restrict__ w0, const float* __restrict__ b0,
        const float* __restrict__ w1, const float* __restrict__ b1) {
    extern __shared__ float sm[];
    float* sW = sm;           // [128][68]
    float* sX = sm + 8704;    // [64][132]

    int z = blockIdx.z;
    int s = z >> 3, b = z & 7;
    const float* x = (s == 0 ? x0 : x1) + (size_t)b * C_IN * NTOK;
    const float* w = (s == 0 ? w0 : w1);
    const float* bias = (s == 0 ? b0 : b1);
    int oy = blockIdx.y, o0 = oy * 128;
    int m0 = blockIdx.x * 128;

    int tid = threadIdx.x;
    int l = tid & 31, wq = tid >> 5;
    int g = l >> 2, j = l & 3;

    float acc[16][4] = {};

    for (int k0 = 0; k0 < C_IN; k0 += 64) {
        for (int u = tid; u < 2048; u += 256) {
            int row = u >> 4, c4 = u & 15;
            float4 t = *(const float4*)(w + (size_t)(o0 + row) * C_IN + k0 + c4 * 4);
            t.x = tf32r(t.x); t.y = tf32r(t.y); t.z = tf32r(t.z); t.w = tf32r(t.w);
            *(float4*)(sW + row * 68 + c4 * 4) = t;
        }
        for (int u = tid; u < 2048; u += 256) {
            int row = u >> 5, m4 = u & 31;
            float4 t = *(const float4*)(x + (size_t)(k0 + row) * NTOK + m0 + m4 * 4);
            t.x = tf32r(t.x); t.y = tf32r(t.y); t.z = tf32r(t.z); t.w = tf32r(t.w);
            *(float4*)(sX + row * 132 + m4 * 4) = t;
        }
        __syncthreads();
#pragma unroll
        for (int ks = 0; ks < 8; ks++) {
            uint32_t a[4];
            const float* wb = sW + (16 * wq + g) * 68 + 8 * ks + j;
            a[0] = __float_as_uint(wb[0]);
            a[1] = __float_as_uint(wb[8 * 68]);
            a[2] = __float_as_uint(wb[4]);
            a[3] = __float_as_uint(wb[8 * 68 + 4]);
            const float* xb0 = sX + (8 * ks + j) * 132 + g;
            const float* xb1 = xb0 + 4 * 132;
#pragma unroll
            for (int nt = 0; nt < 16; nt++)
                mma8(acc[nt], a, __float_as_uint(xb0[8 * nt]), __float_as_uint(xb1[8 * nt]));
        }
        __syncthreads();
    }

    if (oy == 2) {
        // v: channel-major fp16, pairs along n
        int d0 = 16 * wq + g, d1 = d0 + 8;
        float bv0 = bias[256 + d0], bv1 = bias[256 + d1];
        __half* v0 = &g_vh[s][b][d0][0];
        __half* v1 = &g_vh[s][b][d1][0];
#pragma unroll
        for (int nt = 0; nt < 16; nt++) {
            int m = m0 + 8 * nt + 2 * j;
            *(__half2*)(v0 + m) = __floats2half2_rn(acc[nt][0] + bv0, acc[nt][1] + bv0);
            *(__half2*)(v1 + m) = __floats2half2_rn(acc[nt][2] + bv1, acc[nt][3] + bv1);
        }
    } else {
        // q/k: transpose via SMEM to token-major fp16
        float* sT = sm;   // [128 d][129 m]
        int d0 = 16 * wq + g, d1 = d0 + 8;
#pragma unroll
        for (int nt = 0; nt < 16; nt++) {
            int m = 8 * nt + 2 * j;
            sT[d0 * 129 + m]     = acc[nt][0];
            sT[d0 * 129 + m + 1] = acc[nt][1];
            sT[d1 * 129 + m]     = acc[nt][2];
            sT[d1 * 129 + m + 1] = acc[nt][3];
        }
        __syncthreads();
        float scl = (oy == 0) ? QSCL : 1.0f;
        __half* base = (oy == 0) ? &g_qh[s][b][0][0] : &g_kh[s][b][0][0];
        float bv[4];
#pragma unroll
        for (int k = 0; k < 4; k++) bv[k] = bias[o0 + l + 32 * k];
        for (int mrow = wq; mrow < 128; mrow += 8) {
            __half* dst = base + (size_t)(m0 + mrow) * HID;
#pragma unroll
            for (int k = 0; k < 4; k++) {
                int d = l + 32 * k;
                dst[d] = __float2half_rn((sT[d * 129 + mrow] + bv[k]) * scl);
            }
        }
    }
}

// ---------------- head-fold + transpose output weight ----------------
__global__ void weff_kernel(const float* __restrict__ w0, const float* __restrict__ w1) {
    int o = blockIdx.x, s = blockIdx.y;
    const float* w = (s == 0 ? w0 : w1);
    int c = threadIdx.x;
    float acc = 0.f;
#pragma unroll
    for (int k = 0; k < 4; k++) acc += w[(size_t)(c + HID * k) * C_IN + o];
    g_wefft[s][o][c] = tf32r(acc);
}

// =======================================================================
// attention: fp16 mma m16n8k16, 128-key tiles, cp.async double buffer
// SMEM chunk swizzle: chunk(row, cidx) at row*256 + (cidx^(row&7))*16
// =======================================================================
__global__ void __launch_bounds__(256, 1) attn_kernel() {
    extern __shared__ char sc[];   // [2][65536]: kf at +0, vf at +32768

    int tid = threadIdx.x;
    int l = tid & 31, w = tid >> 5;
    int g = l >> 2, j = l & 3;
    int m0 = blockIdx.x * 128;
    int b = blockIdx.y, s = blockIdx.z;
    const __half* Qh = &g_qh[1 - s][b][0][0];
    const __half* Kh = &g_kh[s][b][0][0];
    const __half* Vh = &g_vh[s][b][0][0];

    // ---- cp.async prefetch tile 0 ----
    uint32_t sb = smem_u32(sc);
    int nb0 = tid >> 4;            // base row 0..15 (step 16)
    int cidx = tid & 15;           // 16B chunk within 256B row
    uint32_t kdst = (uint32_t)nb0 * 256 + (uint32_t)((cidx ^ (nb0 & 7)) << 4);
    uint32_t vdst = 32768u + kdst;
    const char* ksrc = (const char*)Kh + (size_t)nb0 * 256 + cidx * 16;
    const char* vsrc = (const char*)Vh + (size_t)nb0 * NTOK * 2 + cidx * 16;
#pragma unroll
    for (int u = 0; u < 8; u++) {
        CP16(sb + kdst + u * 4096, ksrc + (size_t)u * 16 * 256);
        CP16(sb + vdst + u * 4096, vsrc + (size_t)u * 16 * NTOK * 2);
    }
    CP_COMMIT();

    // ---- Q fragments -> registers (direct global, fp16 pairs along c) ----
    uint32_t aq[8][4];
    {
        const uint32_t* q0p = (const uint32_t*)(Qh + (size_t)(m0 + 16 * w + g) * HID);
        const uint32_t* q1p = (const uint32_t*)(Qh + (size_t)(m0 + 16 * w + g + 8) * HID);
#pragma unroll
        for (int ks = 0; ks < 8; ks++) {
            aq[ks][0] = q0p[8 * ks + j];
            aq[ks][1] = q1p[8 * ks + j];
            aq[ks][2] = q0p[8 * ks + j + 4];
            aq[ks][3] = q1p[8 * ks + j + 4];
        }
    }

    float oacc[16][4] = {};
    float psum0 = 0.f, psum1 = 0.f;

    for (int t = 0; t < 18; t++) {
        const char* cb = sc + (size_t)(t & 1) * 65536;
        if (t + 1 < 18) {
            uint32_t nbuf = sb + (uint32_t)((t + 1) & 1) * 65536;
            const char* ks2 = ksrc + (size_t)(t + 1) * 128 * 256;   // +128 keys
            const char* vs2 = vsrc + (size_t)(t + 1) * 256;         // +128*2B along n
#pragma unroll
            for (int u = 0; u < 8; u++) {
                CP16(nbuf + kdst + u * 4096, ks2 + (size_t)u * 16 * 256);
                CP16(nbuf + vdst + u * 4096, vs2 + (size_t)u * 16 * NTOK * 2);
            }
            CP_COMMIT();
            CP_WAIT1();
        } else {
            CP_WAIT0();
        }
        __syncthreads();

        // ---- S = Q K^T : 16 queries x 128 keys per warp ----
        float sacc[16][4] = {};
#pragma unroll
        for (int ks = 0; ks < 8; ks++) {
            uint32_t e0 = (uint32_t)(((2 * ks) ^ g) * 16 + 4 * j);
            uint32_t e1 = (uint32_t)(((2 * ks + 1) ^ g) * 16 + 4 * j);
#pragma unroll
            for (int nt = 0; nt < 16; nt++) {
                const char* kb = cb + (8 * nt + g) * 256;
                mma16(sacc[nt], aq[ks],
                      *(const uint32_t*)(kb + e0), *(const uint32_t*)(kb + e1));
            }
        }

        // ---- softmax: P = exp2(S); pack in-lane into fp16 A fragments ----
        uint32_t ap[8][4];
#pragma unroll
        for (int k2 = 0; k2 < 8; k2++) {
            float p00 = ex2f(sacc[2 * k2][0]),     p01 = ex2f(sacc[2 * k2][1]);
            float p02 = ex2f(sacc[2 * k2][2]),     p03 = ex2f(sacc[2 * k2][3]);
            float p10 = ex2f(sacc[2 * k2 + 1][0]), p11 = ex2f(sacc[2 * k2 + 1][1]);
            float p12 = ex2f(sacc[2 * k2 + 1][2]), p13 = ex2f(sacc[2 * k2 + 1][3]);
            psum0 += p00 + p01 + p10 + p11;
            psum1 += p02 + p03 + p12 + p13;
            ap[k2][0] = packh(p00, p01);
            ap[k2][1] = packh(p02, p03);
            ap[k2][2] = packh(p10, p11);
            ap[k2][3] = packh(p12, p13);
        }

        // ---- O += P V ----
        const char* vfp = cb + 32768;
#pragma unroll
        for (int k2 = 0; k2 < 8; k2++) {
            uint32_t e0 = (uint32_t)(((2 * k2) ^ g) * 16 + 4 * j);
            uint32_t e1 = (uint32_t)(((2 * k2 + 1) ^ g) * 16 + 4 * j);
#pragma unroll
            for (int dt = 0; dt < 16; dt++) {
                const char* vb = vfp + (8 * dt + g) * 256;
                mma16(oacc[dt], ap[k2],
                      *(const uint32_t*)(vb + e0), *(const uint32_t*)(vb + e1));
            }
        }
        __syncthreads();   // all warps done reading before this buffer is refilled
    }

    // ---- epilogue: normalize rows, tf32-round, write h ----
    psum0 += __shfl_xor_sync(0xffffffffu, psum0, 1);
    psum0 += __shfl_xor_sync(0xffffffffu, psum0, 2);
    psum1 += __shfl_xor_sync(0xffffffffu, psum1, 1);
    psum1 += __shfl_xor_sync(0xffffffffu, psum1, 2);
    float inv0 = 1.f / psum0, inv1 = 1.f / psum1;

    int q0 = m0 + 16 * w + g;
    float* h0 = &g_h[s][b][q0][0];
    float* h1 = &g_h[s][b][q0 + 8][0];
#pragma unroll
    for (int dt = 0; dt < 16; dt++) {
        *(float2*)(h0 + 8 * dt + 2 * j) =
            make_float2(tf32r(oacc[dt][0] * inv0), tf32r(oacc[dt][1] * inv0));
        *(float2*)(h1 + 8 * dt + 2 * j) =
            make_float2(tf32r(oacc[dt][2] * inv1), tf32r(oacc[dt][3] * inv1));
    }
}

// =======================================================================
// out (tf32 mma): out[o][m] = sum_c Wt[o][c] H[m][c] + bias[o] + x[o][m]
// =======================================================================
__global__ void __launch_bounds__(256, 2) out_kernel(
        const float* __restrict__ x0, const float* __restrict__ x1,
        const float* __restrict__ ob0, const float* __restrict__ ob1,
        float* __restrict__ out) {
    extern __shared__ float sm[];
    float* sWe = sm;          // [128][68]
    float* sH  = sm + 8704;   // [128][68]

    int z = blockIdx.z;
    int s = z >> 3, b = z & 7;
    const float* x = (s == 0 ? x0 : x1) + (size_t)b * C_IN * NTOK;
    const float* ob = (s == 0 ? ob0 : ob1);
    float* o_out = out + (size_t)s * NB * C_IN * NTOK + (size_t)b * C_IN * NTOK;
    int ot = blockIdx.y;
    int m0 = blockIdx.x * 128;
    const float* Wt = &g_wefft[s][ot * 128][0];
    const float* H = &g_h[s][b][0][0];

    int tid = threadIdx.x;
    int l = tid & 31, wq = tid >> 5;
    int g = l >> 2, j = l & 3;

    float acc[16][4] = {};

    for (int c0 = 0; c0 < HID; c0 += 64) {
        for (int u = tid; u < 2048; u += 256) {
            int row = u >> 4, c4 = u & 15;
            *(float4*)(sWe + row * 68 + c4 * 4) =
                *(const float4*)(Wt + (size_t)row * HID + c0 + c4 * 4);
        }
        for (int u = tid; u < 2048; u += 256) {
            int row = u >> 4, c4 = u & 15;
            *(float4*)(sH + row * 68 + c4 * 4) =
                *(const float4*)(H + (size_t)(m0 + row) * HID + c0 + c4 * 4);
        }
        __syncthreads();
#pragma unroll
        for (int ks = 0; ks < 8; ks++) {
            uint32_t a[4];
            const float* wb = sWe + (16 * wq + g) * 68 + 8 * ks + j;
            a[0] = __float_as_uint(wb[0]);
            a[1] = __float_as_uint(wb[8 * 68]);
            a[2] = __float_as_uint(wb[4]);
            a[3] = __float_as_uint(wb[8 * 68 + 4]);
            const float* hb0 = sH + g * 68 + 8 * ks + j;
            const float* hb1 = hb0 + 4;
#pragma unroll
            for (int nt = 0; nt < 16; nt++)
                mma8(acc[nt], a,
                     __float_as_uint(hb0[nt * 8 * 68]),
                     __float_as_uint(hb1[nt * 8 * 68]));
        }
        __syncthreads();
    }

    int o_a = ot * 128 + 16 * wq + g, o_b = o_a + 8;
    float bva = ob[o_a], bvb = ob[o_b];
#pragma unroll
    for (int nt = 0; nt < 16; nt++) {
        int m = m0 + 8 * nt + 2 * j;
        size_t ia = (size_t)o_a * NTOK + m;
        size_t ib = (size_t)o_b * NTOK + m;
        float2 xa = *(const float2*)(x + ia);
        float2 xb = *(const float2*)(x + ib);
        *(float2*)(o_out + ia) = make_float2(acc[nt][0] + bva + xa.x, acc[nt][1] + bva + xa.y);
        *(float2*)(o_out + ib) = make_float2(acc[nt][2] + bvb + xb.x, acc[nt][3] + bvb + xb.y);
    }
}

// ---------------- launch ----------------
extern "C" void kernel_launch(void* const* d_in, const int* in_sizes, int n_in,
                              void* d_out, int out_size) {
    const float* x0  = (const float*)d_in[0];
    const float* x1  = (const float*)d_in[1];
    const float* ew0 = (const float*)d_in[2];
    const float* eb0 = (const float*)d_in[3];
    const float* ew1 = (const float*)d_in[4];
    const float* eb1 = (const float*)d_in[5];
    const float* ow0 = (const float*)d_in[6];
    const float* ob0 = (const float*)d_in[7];
    const float* ow1 = (const float*)d_in[8];
    const float* ob1 = (const float*)d_in[9];
    float* out = (float*)d_out;

    int smem_e = 17152 * 4;
    cudaFuncSetAttribute(embed_kernel, cudaFuncAttributeMaxDynamicSharedMemorySize, smem_e);
    embed_kernel<<<dim3(NTOK / 128, 3, 16), 256, smem_e>>>(x0, x1, ew0, eb0, ew1, eb1);

    weff_kernel<<<dim3(C_IN, NSTREAMS), HID>>>(ow0, ow1);

    int smem_a = 2 * 65536;
    cudaFuncSetAttribute(attn_kernel, cudaFuncAttributeMaxDynamicSharedMemorySize, smem_a);
    attn_kernel<<<dim3(NTOK / 128, NB, NSTREAMS), 256, smem_a>>>();

    int smem_o = 17408 * 4;
    cudaFuncSetAttribute(out_kernel, cudaFuncAttributeMaxDynamicSharedMemorySize, smem_o);
    out_kernel<<<dim3(NTOK / 128, 2, 16), 256, smem_o>>>(x0, x1, ob0, ob1, out);
}

// round 12
// speedup vs baseline: 11.6446x; 1.2477x over previous
#include <cuda_runtime.h>
#include <cuda_fp16.h>
#include <cstdint>

#define NSTREAMS 2
#define NB 8
#define C_IN 256
#define HID 128
#define NTOK 2304
#define QSCL 0.09016844005f   // 256^-0.5 * log2(e), folded into q at embed time

// ---------------- scratch (device globals; no allocs allowed) ----------------
__device__ __half   g_qh[NSTREAMS][NB][NTOK][HID];  // token-major, scaled, fp16
__device__ __half   g_kh[NSTREAMS][NB][NTOK][HID];  // token-major, fp16
__device__ __half   g_vh[NSTREAMS][NB][HID][NTOK];  // channel-major, fp16
__device__ uint32_t g_w2[NSTREAMS][C_IN][HID / 2];  // W_eff [o][c2] half2 (c even lo)

// ---------------- helpers ----------------
__device__ __forceinline__ float ex2f(float x) {
    float y; asm("ex2.approx.ftz.f32 %0, %1;" : "=f"(y) : "f"(x)); return y;
}
__device__ __forceinline__ uint32_t packh(float lo, float hi) {
    uint32_t d; asm("cvt.rn.f16x2.f32 %0, %1, %2;" : "=r"(d) : "f"(hi), "f"(lo));
    return d;
}
__device__ __forceinline__ void mma16(float c[4], const uint32_t a[4],
                                      uint32_t b0, uint32_t b1) {
    asm volatile(
        "mma.sync.aligned.m16n8k16.row.col.f32.f16.f16.f32 "
        "{%0,%1,%2,%3}, {%4,%5,%6,%7}, {%8,%9}, {%0,%1,%2,%3};"
        : "+f"(c[0]), "+f"(c[1]), "+f"(c[2]), "+f"(c[3])
        : "r"(a[0]), "r"(a[1]), "r"(a[2]), "r"(a[3]), "r"(b0), "r"(b1));
}
__device__ __forceinline__ uint32_t smem_u32(const void* p) {
    uint32_t a;
    asm("{ .reg .u64 t; cvta.to.shared.u64 t, %1; cvt.u32.u64 %0, t; }" : "=r"(a) : "l"(p));
    return a;
}
#define CP16(dst, src) asm volatile("cp.async.cg.shared.global [%0], [%1], 16;" :: "r"(dst), "l"(src))
#define CP_COMMIT()    asm volatile("cp.async.commit_group;" ::: "memory")
#define CP_WAIT1()     asm volatile("cp.async.wait_group 1;" ::: "memory")
#define CP_WAIT0()     asm volatile("cp.async.wait_group 0;" ::: "memory")

// =======================================================================
// embed (fp16 mma m16n8k16): E[o][m] = sum_c W[o][c] X[c][m]
// oy selects q / k / v.  CTA: 128o x 128m, K chunks of 64.
// =======================================================================
__global__ void __launch_bounds__(256, 2) embed_kernel(
        const float* __restrict__ x0, const float* __restrict__ x1,
        const float* __restrict__ w0, const float* __restrict__ b0,
        const float* __restrict__ w1, const float* __restrict__ b1) {
    extern __shared__ char esm[];
    uint32_t* sW2 = (uint32_t*)esm;                    // [128][36]  half2 pairs along c
    uint32_t* sX2 = (uint32_t*)(esm + 128 * 36 * 4);   // [32][136]  half2 pairs along c
    float* sT = (float*)esm;                           // [128][129] (phase 2 reuse)

    int z = blockIdx.z;
    int s = z >> 3, b = z & 7;
    const float* x = (s == 0 ? x0 : x1) + (size_t)b * C_IN * NTOK;
    const float* w = (s == 0 ? w0 : w1);
    const float* bias = (s == 0 ? b0 : b1);
    int oy = blockIdx.y, o0 = oy * 128;
    int m0 = blockIdx.x * 128;

    int tid = threadIdx.x;
    int l = tid & 31, wq = tid >> 5;
    int g = l >> 2, j = l & 3;

    float acc[16][4] = {};

    for (int k0 = 0; k0 < C_IN; k0 += 64) {
        for (int u = tid; u < 4096; u += 256) {        // W: 128 o-rows x 32 c2
            int row = u >> 5, c2 = u & 31;
            float2 f = *(const float2*)(w + (size_t)(o0 + row) * C_IN + k0 + 2 * c2);
            sW2[row * 36 + c2] = packh(f.x, f.y);
        }
        for (int u = tid; u < 1024; u += 256) {        // X: 32 k2-rows x 32 m4
            int k2 = u >> 5, m4 = u & 31;
            const float* xa = x + (size_t)(k0 + 2 * k2) * NTOK + m0 + 4 * m4;
            float4 fa = *(const float4*)xa;
            float4 fb = *(const float4*)(xa + NTOK);
            uint4 p;
            p.x = packh(fa.x, fb.x); p.y = packh(fa.y, fb.y);
            p.z = packh(fa.z, fb.z); p.w = packh(fa.w, fb.w);
            *(uint4*)(sX2 + k2 * 136 + 4 * m4) = p;
        }
        __syncthreads();
#pragma unroll
        for (int ks = 0; ks < 4; ks++) {
            uint32_t a[4];
            const uint32_t* wb = sW2 + (16 * wq + g) * 36 + 8 * ks + j;
            a[0] = wb[0];
            a[1] = wb[8 * 36];
            a[2] = wb[4];
            a[3] = wb[8 * 36 + 4];
            const uint32_t* xb0 = sX2 + (8 * ks + j) * 136 + g;
            const uint32_t* xb1 = sX2 + (8 * ks + 4 + j) * 136 + g;
#pragma unroll
            for (int nt = 0; nt < 16; nt++)
                mma16(acc[nt], a, xb0[8 * nt], xb1[8 * nt]);
        }
        __syncthreads();
    }

    if (oy == 2) {
        // v: channel-major fp16, pairs along n
        int d0 = 16 * wq + g, d1 = d0 + 8;
        float bv0 = bias[256 + d0], bv1 = bias[256 + d1];
        __half* v0 = &g_vh[s][b][d0][0];
        __half* v1 = &g_vh[s][b][d1][0];
#pragma unroll
        for (int nt = 0; nt < 16; nt++) {
            int m = m0 + 8 * nt + 2 * j;
            *(__half2*)(v0 + m) = __floats2half2_rn(acc[nt][0] + bv0, acc[nt][1] + bv0);
            *(__half2*)(v1 + m) = __floats2half2_rn(acc[nt][2] + bv1, acc[nt][3] + bv1);
        }
    } else {
        // q/k: transpose via SMEM to token-major fp16
        int d0 = 16 * wq + g, d1 = d0 + 8;
#pragma unroll
        for (int nt = 0; nt < 16; nt++) {
            int m = 8 * nt + 2 * j;
            sT[d0 * 129 + m]     = acc[nt][0];
            sT[d0 * 129 + m + 1] = acc[nt][1];
            sT[d1 * 129 + m]     = acc[nt][2];
            sT[d1 * 129 + m + 1] = acc[nt][3];
        }
        __syncthreads();
        float scl = (oy == 0) ? QSCL : 1.0f;
        __half* base = (oy == 0) ? &g_qh[s][b][0][0] : &g_kh[s][b][0][0];
        float bv[4];
#pragma unroll
        for (int k = 0; k < 4; k++) bv[k] = bias[o0 + l + 32 * k];
        for (int mrow = wq; mrow < 128; mrow += 8) {
            __half* dst = base + (size_t)(m0 + mrow) * HID;
#pragma unroll
            for (int k = 0; k < 4; k++) {
                int d = l + 32 * k;
                dst[d] = __float2half_rn((sT[d * 129 + mrow] + bv[k]) * scl);
            }
        }
    }
}

// ---------------- head-fold output weight -> fp16 pairs [o][c2] ----------------
__global__ void weff_kernel(const float* __restrict__ w0, const float* __restrict__ w1) {
    int k2 = blockIdx.x;           // 0..63
    int s = blockIdx.y;
    int o = threadIdx.x;           // 0..255
    const float* w = (s == 0 ? w0 : w1);
    float e = 0.f, d = 0.f;
#pragma unroll
    for (int h = 0; h < 4; h++) {
        e += w[(size_t)(2 * k2 + HID * h) * C_IN + o];
        d += w[(size_t)(2 * k2 + 1 + HID * h) * C_IN + o];
    }
    g_w2[s][o][k2] = packh(e, d);
}

// =======================================================================
// attention + fused output projection.
// fp16 mma, 128-key tiles, cp.async double buffer; last iteration
// prefetches W_eff (chunk-XOR swizzled) into the dead buffer half.
// Epilogue: Out = Weff * H directly from O-accumulator registers.
// =======================================================================
__global__ void __launch_bounds__(256, 1) attn_kernel(
        const float* __restrict__ x0, const float* __restrict__ x1,
        const float* __restrict__ ob0, const float* __restrict__ ob1,
        float* __restrict__ out) {
    extern __shared__ char sc[];   // [2][65536]: kf at +0, vf at +32768 per buffer

    int tid = threadIdx.x;
    int l = tid & 31, w = tid >> 5;
    int g = l >> 2, j = l & 3;
    int m0 = blockIdx.x * 128;
    int b = blockIdx.y, s = blockIdx.z;
    const __half* Qh = &g_qh[1 - s][b][0][0];
    const __half* Kh = &g_kh[s][b][0][0];
    const __half* Vh = &g_vh[s][b][0][0];
    const float* x = (s == 0 ? x0 : x1) + (size_t)b * C_IN * NTOK;
    const float* ob = (s == 0 ? ob0 : ob1);
    float* oo = out + ((size_t)s * NB + b) * C_IN * NTOK;

    // ---- cp.async prefetch tile 0 ----
    uint32_t sb = smem_u32(sc);
    int nb0 = tid >> 4;            // base row 0..15 (step 16)
    int cidx = tid & 15;           // 16B chunk within 256B row
    uint32_t kdst = (uint32_t)nb0 * 256 + (uint32_t)((cidx ^ (nb0 & 7)) << 4);
    uint32_t vdst = 32768u + kdst;
    const char* ksrc = (const char*)Kh + (size_t)nb0 * 256 + cidx * 16;
    const char* vsrc = (const char*)Vh + (size_t)nb0 * NTOK * 2 + cidx * 16;
#pragma unroll
    for (int u = 0; u < 8; u++) {
        CP16(sb + kdst + u * 4096, ksrc + (size_t)u * 16 * 256);
        CP16(sb + vdst + u * 4096, vsrc + (size_t)u * 16 * NTOK * 2);
    }
    CP_COMMIT();

    // ---- Q fragments -> registers ----
    uint32_t aq[8][4];
    {
        const uint32_t* q0p = (const uint32_t*)(Qh + (size_t)(m0 + 16 * w + g) * HID);
        const uint32_t* q1p = (const uint32_t*)(Qh + (size_t)(m0 + 16 * w + g + 8) * HID);
#pragma unroll
        for (int ks = 0; ks < 8; ks++) {
            aq[ks][0] = q0p[8 * ks + j];
            aq[ks][1] = q1p[8 * ks + j];
            aq[ks][2] = q0p[8 * ks + j + 4];
            aq[ks][3] = q1p[8 * ks + j + 4];
        }
    }

    float oacc[16][4] = {};
    float psum0 = 0.f, psum1 = 0.f;

    for (int t = 0; t < 18; t++) {
        const char* cb = sc + (size_t)(t & 1) * 65536;
        if (t + 1 < 18) {
            uint32_t nbuf = sb + (uint32_t)((t + 1) & 1) * 65536;
            const char* ks2 = ksrc + (size_t)(t + 1) * 128 * 256;
            const char* vs2 = vsrc + (size_t)(t + 1) * 256;
#pragma unroll
            for (int u = 0; u < 8; u++) {
                CP16(nbuf + kdst + u * 4096, ks2 + (size_t)u * 16 * 256);
                CP16(nbuf + vdst + u * 4096, vs2 + (size_t)u * 16 * NTOK * 2);
            }
            CP_COMMIT();
            CP_WAIT1();
        } else {
            // last iter: prefetch W_eff [256 o][64 k2] into buf0 (dead),
            // chunk-XOR swizzle: word = o*64 + (k2 ^ 4*(o&7))
            const char* wsrc = (const char*)&g_w2[s][0][0];
#pragma unroll
            for (int u = 0; u < 16; u++) {
                int idx = tid + 256 * u;
                int row = idx >> 4, ch = idx & 15;
                CP16(sb + (uint32_t)row * 256 + (uint32_t)((ch ^ (row & 7)) << 4),
                     wsrc + (size_t)idx * 16);
            }
            CP_COMMIT();
            CP_WAIT1();
        }
        __syncthreads();

        // ---- S = Q K^T : 16 queries x 128 keys per warp ----
        float sacc[16][4] = {};
#pragma unroll
        for (int ks = 0; ks < 8; ks++) {
            uint32_t e0 = (uint32_t)(((2 * ks) ^ g) * 16 + 4 * j);
            uint32_t e1 = (uint32_t)(((2 * ks + 1) ^ g) * 16 + 4 * j);
#pragma unroll
            for (int nt = 0; nt < 16; nt++) {
                const char* kb = cb + (8 * nt + g) * 256;
                mma16(sacc[nt], aq[ks],
                      *(const uint32_t*)(kb + e0), *(const uint32_t*)(kb + e1));
            }
        }

        // ---- softmax: P = exp2(S); pack in-lane into fp16 A fragments ----
        uint32_t ap[8][4];
#pragma unroll
        for (int k2 = 0; k2 < 8; k2++) {
            float p00 = ex2f(sacc[2 * k2][0]),     p01 = ex2f(sacc[2 * k2][1]);
            float p02 = ex2f(sacc[2 * k2][2]),     p03 = ex2f(sacc[2 * k2][3]);
            float p10 = ex2f(sacc[2 * k2 + 1][0]), p11 = ex2f(sacc[2 * k2 + 1][1]);
            float p12 = ex2f(sacc[2 * k2 + 1][2]), p13 = ex2f(sacc[2 * k2 + 1][3]);
            psum0 += p00 + p01 + p10 + p11;
            psum1 += p02 + p03 + p12 + p13;
            ap[k2][0] = packh(p00, p01);
            ap[k2][1] = packh(p02, p03);
            ap[k2][2] = packh(p10, p11);
            ap[k2][3] = packh(p12, p13);
        }

        // ---- O += P V ----
        const char* vfp = cb + 32768;
#pragma unroll
        for (int k2 = 0; k2 < 8; k2++) {
            uint32_t e0 = (uint32_t)(((2 * k2) ^ g) * 16 + 4 * j);
            uint32_t e1 = (uint32_t)(((2 * k2 + 1) ^ g) * 16 + 4 * j);
#pragma unroll
            for (int dt = 0; dt < 16; dt++) {
                const char* vb = vfp + (8 * dt + g) * 256;
                mma16(oacc[dt], ap[k2],
                      *(const uint32_t*)(vb + e0), *(const uint32_t*)(vb + e1));
            }
        }
        __syncthreads();
    }

    // ---- W_eff arrived; make visible to all threads ----
    CP_WAIT0();
    __syncthreads();

    // ---- normalize rows, pack O into out-GEMM B fragments (in-lane) ----
    psum0 += __shfl_xor_sync(0xffffffffu, psum0, 1);
    psum0 += __shfl_xor_sync(0xffffffffu, psum0, 2);
    psum1 += __shfl_xor_sync(0xffffffffu, psum1, 1);
    psum1 += __shfl_xor_sync(0xffffffffu, psum1, 2);
    float inv0 = 1.f / psum0, inv1 = 1.f / psum1;

    uint32_t bp0[8][2], bp1[8][2];
#pragma unroll
    for (int kk = 0; kk < 8; kk++) {
        bp0[kk][0] = packh(oacc[2 * kk][0] * inv0,     oacc[2 * kk][1] * inv0);
        bp0[kk][1] = packh(oacc[2 * kk + 1][0] * inv0, oacc[2 * kk + 1][1] * inv0);
        bp1[kk][0] = packh(oacc[2 * kk][2] * inv1,     oacc[2 * kk][3] * inv1);
        bp1[kk][1] = packh(oacc[2 * kk + 1][2] * inv1, oacc[2 * kk + 1][3] * inv1);
    }

    // ---- Out[o][m] = Weff H + bias + x : A = Weff (SMEM), B = bp (regs) ----
    const uint32_t* w32 = (const uint32_t*)sc;
#pragma unroll
    for (int ot = 0; ot < 16; ot++) {
        float ac0[4] = {}, ac1[4] = {};
        int r0 = (16 * ot + g) * 64, r1 = (16 * ot + 8 + g) * 64;
#pragma unroll
        for (int kk = 0; kk < 8; kk++) {
            uint32_t a[4];
            int e0 = (8 * kk + j) ^ (4 * g);
            int e1 = (8 * kk + 4 + j) ^ (4 * g);
            a[0] = w32[r0 + e0];
            a[1] = w32[r1 + e0];
            a[2] = w32[r0 + e1];
            a[3] = w32[r1 + e1];
            mma16(ac0, a, bp0[kk][0], bp0[kk][1]);
            mma16(ac1, a, bp1[kk][0], bp1[kk][1]);
        }
        int oa = 16 * ot + g, obr = oa + 8;
        float ba = ob[oa], bb = ob[obr];
        int mA = m0 + 16 * w + 2 * j;
        const float* xr0 = x + (size_t)oa * NTOK + mA;
        const float* xr1 = x + (size_t)obr * NTOK + mA;
        float* or0 = oo + (size_t)oa * NTOK + mA;
        float* or1 = oo + (size_t)obr * NTOK + mA;
        float2 q00 = *(const float2*)xr0, q01 = *(const float2*)(xr0 + 8);
        float2 q10 = *(const float2*)xr1, q11 = *(const float2*)(xr1 + 8);
        *(float2*)or0       = make_float2(ac0[0] + ba + q00.x, ac0[1] + ba + q00.y);
        *(float2*)(or0 + 8) = make_float2(ac1[0] + ba + q01.x, ac1[1] + ba + q01.y);
        *(float2*)or1       = make_float2(ac0[2] + bb + q10.x, ac0[3] + bb + q10.y);
        *(float2*)(or1 + 8) = make_float2(ac1[2] + bb + q11.x, ac1[3] + bb + q11.y);
    }
}

// ---------------- launch ----------------
extern "C" void kernel_launch(void* const* d_in, const int* in_sizes, int n_in,
                              void* d_out, int out_size) {
    const float* x0  = (const float*)d_in[0];
    const float* x1  = (const float*)d_in[1];
    const float* ew0 = (const float*)d_in[2];
    const float* eb0 = (const float*)d_in[3];
    const float* ew1 = (const float*)d_in[4];
    const float* eb1 = (const float*)d_in[5];
    const float* ow0 = (const float*)d_in[6];
    const float* ob0 = (const float*)d_in[7];
    const float* ow1 = (const float*)d_in[8];
    const float* ob1 = (const float*)d_in[9];
    float* out = (float*)d_out;

    int smem_e = 128 * 129 * 4;   // 66048 (union with fragment staging)
    cudaFuncSetAttribute(embed_kernel, cudaFuncAttributeMaxDynamicSharedMemorySize, smem_e);
    embed_kernel<<<dim3(NTOK / 128, 3, 16), 256, smem_e>>>(x0, x1, ew0, eb0, ew1, eb1);

    weff_kernel<<<dim3(HID / 2, NSTREAMS), C_IN>>>(ow0, ow1);

    int smem_a = 2 * 65536;
    cudaFuncSetAttribute(attn_kernel, cudaFuncAttributeMaxDynamicSharedMemorySize, smem_a);
    attn_kernel<<<dim3(NTOK / 128, NB, NSTREAMS), 256, smem_a>>>(x0, x1, ob0, ob1, out);
}

// round 13
// speedup vs baseline: 13.1834x; 1.1321x over previous
#include <cuda_runtime.h>
#include <cuda_fp16.h>
#include <cstdint>

#define NSTREAMS 2
#define NB 8
#define C_IN 256
#define HID 128
#define NTOK 2304
#define QSCL 0.09016844005f   // 256^-0.5 * log2(e), folded into q (via wh rows o<128)

// ---------------- scratch (device globals; no allocs allowed) ----------------
__device__ __half   g_qh[NSTREAMS][NB][NTOK][HID];  // token-major, scaled, fp16
__device__ __half   g_kh[NSTREAMS][NB][NTOK][HID];  // token-major, fp16
__device__ __half   g_vh[NSTREAMS][NB][HID][NTOK];  // channel-major, fp16
__device__ uint32_t g_w2[NSTREAMS][C_IN][HID / 2];  // W_eff [o][c2] half2 (c even lo)
__device__ uint32_t g_wh[NSTREAMS][384][C_IN / 2];  // embed W fp16 pairs [o][c2]

// ---------------- helpers ----------------
__device__ __forceinline__ float ex2f(float x) {
    float y; asm("ex2.approx.ftz.f32 %0, %1;" : "=f"(y) : "f"(x)); return y;
}
__device__ __forceinline__ uint32_t packh(float lo, float hi) {
    uint32_t d; asm("cvt.rn.f16x2.f32 %0, %1, %2;" : "=r"(d) : "f"(hi), "f"(lo));
    return d;
}
__device__ __forceinline__ void mma16(float c[4], const uint32_t a[4],
                                      uint32_t b0, uint32_t b1) {
    asm volatile(
        "mma.sync.aligned.m16n8k16.row.col.f32.f16.f16.f32 "
        "{%0,%1,%2,%3}, {%4,%5,%6,%7}, {%8,%9}, {%0,%1,%2,%3};"
        : "+f"(c[0]), "+f"(c[1]), "+f"(c[2]), "+f"(c[3])
        : "r"(a[0]), "r"(a[1]), "r"(a[2]), "r"(a[3]), "r"(b0), "r"(b1));
}
__device__ __forceinline__ uint32_t smem_u32(const void* p) {
    uint32_t a;
    asm("{ .reg .u64 t; cvta.to.shared.u64 t, %1; cvt.u32.u64 %0, t; }" : "=r"(a) : "l"(p));
    return a;
}
#define CP16(dst, src) asm volatile("cp.async.cg.shared.global [%0], [%1], 16;" :: "r"(dst), "l"(src))
#define CP_COMMIT()    asm volatile("cp.async.commit_group;" ::: "memory")
#define CP_WAIT1()     asm volatile("cp.async.wait_group 1;" ::: "memory")
#define CP_WAIT0()     asm volatile("cp.async.wait_group 0;" ::: "memory")

// ---------------- pre-convert embed weight to fp16 pairs (QSCL folded for q) ----------------
__global__ void wh_kernel(const float* __restrict__ w0, const float* __restrict__ w1) {
    int o = blockIdx.x;            // 0..383
    int s = blockIdx.y;
    const float* w = (s == 0 ? w0 : w1) + (size_t)o * C_IN;
    float scl = (o < HID) ? QSCL : 1.0f;
    int c2 = threadIdx.x;          // 0..127
    g_wh[s][o][c2] = packh(w[2 * c2] * scl, w[2 * c2 + 1] * scl);
}

// =======================================================================
// embed (fp16 mma): one CTA computes q,k,v for a 64-token m-tile.
// X staged once per 64-c chunk (half2 pairs); W via cp.async (swizzled).
// =======================================================================
__global__ void __launch_bounds__(256, 2) embed_kernel(
        const float* __restrict__ x0, const float* __restrict__ x1,
        const float* __restrict__ b0_, const float* __restrict__ b1_) {
    extern __shared__ char esm[];
    uint32_t* sX = (uint32_t*)esm;          // [32 c2][72 pad] half2 words
    char* wsm = esm + 9216;                 // 3 oy x 16384 B, chunk-XOR swizzled
    float* sT = (float*)(esm + 9216);       // [128 d][66 m] transpose overlay

    int z = blockIdx.y;
    int s = z >> 3, b = z & 7;
    const float* x = (s == 0 ? x0 : x1) + (size_t)b * C_IN * NTOK;
    const float* bias = (s == 0 ? b0_ : b1_);
    const uint32_t* wh = &g_wh[s][0][0];
    int m0 = blockIdx.x * 64;
    int tid = threadIdx.x;
    int l = tid & 31, wq = tid >> 5;
    int g = l >> 2, j = l & 3;
    uint32_t sb = smem_u32(esm);

    float acc[3][8][4] = {};

    for (int c = 0; c < 4; c++) {
        int k0 = 64 * c;
        // W: 3 oy x 128 rows x 8 chunks of 16B, swizzled chunk^(row&7)
#pragma unroll
        for (int u = 0; u < 12; u++) {
            int idx = tid + 256 * u;
            int oyi = idx >> 10, rem = idx & 1023;
            int row = rem >> 3, ch = rem & 7;
            uint32_t dst = sb + 9216u + (uint32_t)oyi * 16384u
                         + (uint32_t)row * 128u + (uint32_t)((ch ^ (row & 7)) << 4);
            const char* src = (const char*)(wh + (size_t)(oyi * 128 + row) * 128
                                            + (k0 >> 1) + ch * 4);
            CP16(dst, src);
        }
        CP_COMMIT();
        // X: 32 c2-rows x 16 f4-of-m, packed half2 along c
#pragma unroll
        for (int u = 0; u < 2; u++) {
            int idx = tid + 256 * u;
            int k2 = idx >> 4, m4 = idx & 15;
            const float* xa = x + (size_t)(k0 + 2 * k2) * NTOK + m0 + 4 * m4;
            float4 fa = *(const float4*)xa;
            float4 fb = *(const float4*)(xa + NTOK);
            uint4 p;
            p.x = packh(fa.x, fb.x); p.y = packh(fa.y, fb.y);
            p.z = packh(fa.z, fb.z); p.w = packh(fa.w, fb.w);
            *(uint4*)(sX + k2 * 72 + 4 * m4) = p;
        }
        CP_WAIT0();
        __syncthreads();
#pragma unroll
        for (int oy = 0; oy < 3; oy++) {
            const char* wrow0 = wsm + oy * 16384 + (16 * wq + g) * 128;
            const char* wrow1 = wrow0 + 8 * 128;
#pragma unroll
            for (int ks = 0; ks < 4; ks++) {
                int e0 = ((2 * ks) ^ g) * 16 + 4 * j;
                int e1 = ((2 * ks + 1) ^ g) * 16 + 4 * j;
                uint32_t a[4];
                a[0] = *(const uint32_t*)(wrow0 + e0);
                a[1] = *(const uint32_t*)(wrow1 + e0);
                a[2] = *(const uint32_t*)(wrow0 + e1);
                a[3] = *(const uint32_t*)(wrow1 + e1);
                const uint32_t* xb0 = sX + (8 * ks + j) * 72 + g;
                const uint32_t* xb1 = sX + (8 * ks + 4 + j) * 72 + g;
#pragma unroll
                for (int nt = 0; nt < 8; nt++)
                    mma16(acc[oy][nt], a, xb0[8 * nt], xb1[8 * nt]);
            }
        }
        __syncthreads();
    }

    // ---- epilogue v (oy=2): channel-major fp16, pairs along m ----
    {
        int d0 = 16 * wq + g, d1 = d0 + 8;
        float bv0 = bias[256 + d0], bv1 = bias[256 + d1];
        __half* v0 = &g_vh[s][b][d0][0];
        __half* v1 = &g_vh[s][b][d1][0];
#pragma unroll
        for (int nt = 0; nt < 8; nt++) {
            int m = m0 + 8 * nt + 2 * j;
            *(__half2*)(v0 + m) = __floats2half2_rn(acc[2][nt][0] + bv0, acc[2][nt][1] + bv0);
            *(__half2*)(v1 + m) = __floats2half2_rn(acc[2][nt][2] + bv1, acc[2][nt][3] + bv1);
        }
    }
    // ---- epilogue q (oy=0) / k (oy=1): transpose to token-major fp16 ----
#pragma unroll
    for (int oy = 0; oy < 2; oy++) {
        __syncthreads();
        int d0 = 16 * wq + g, d1 = d0 + 8;
#pragma unroll
        for (int nt = 0; nt < 8; nt++) {
            int m = 8 * nt + 2 * j;
            *(float2*)(sT + d0 * 66 + m) = make_float2(acc[oy][nt][0], acc[oy][nt][1]);
            *(float2*)(sT + d1 * 66 + m) = make_float2(acc[oy][nt][2], acc[oy][nt][3]);
        }
        __syncthreads();
        float bscl = (oy == 0) ? QSCL : 1.0f;   // acc already scaled via wh for q
        __half* base = (oy == 0) ? &g_qh[s][b][0][0] : &g_kh[s][b][0][0];
        float bv[4];
#pragma unroll
        for (int k = 0; k < 4; k++) bv[k] = bias[oy * 128 + l + 32 * k] * bscl;
        for (int mrow = wq; mrow < 64; mrow += 8) {
            __half* dst = base + (size_t)(m0 + mrow) * HID;
#pragma unroll
            for (int k = 0; k < 4; k++) {
                int d = l + 32 * k;
                dst[d] = __float2half_rn(sT[d * 66 + mrow] + bv[k]);
            }
        }
    }
}

// ---------------- head-fold output weight -> fp16 pairs [o][c2] ----------------
__global__ void weff_kernel(const float* __restrict__ w0, const float* __restrict__ w1) {
    int k2 = blockIdx.x;           // 0..63
    int s = blockIdx.y;
    int o = threadIdx.x;           // 0..255
    const float* w = (s == 0 ? w0 : w1);
    float e = 0.f, d = 0.f;
#pragma unroll
    for (int h = 0; h < 4; h++) {
        e += w[(size_t)(2 * k2 + HID * h) * C_IN + o];
        d += w[(size_t)(2 * k2 + 1 + HID * h) * C_IN + o];
    }
    g_w2[s][o][k2] = packh(e, d);
}

// =======================================================================
// attention + fused output projection (unchanged from R12).
// =======================================================================
__global__ void __launch_bounds__(256, 1) attn_kernel(
        const float* __restrict__ x0, const float* __restrict__ x1,
        const float* __restrict__ ob0, const float* __restrict__ ob1,
        float* __restrict__ out) {
    extern __shared__ char sc[];   // [2][65536]: kf at +0, vf at +32768 per buffer

    int tid = threadIdx.x;
    int l = tid & 31, w = tid >> 5;
    int g = l >> 2, j = l & 3;
    int m0 = blockIdx.x * 128;
    int b = blockIdx.y, s = blockIdx.z;
    const __half* Qh = &g_qh[1 - s][b][0][0];
    const __half* Kh = &g_kh[s][b][0][0];
    const __half* Vh = &g_vh[s][b][0][0];
    const float* x = (s == 0 ? x0 : x1) + (size_t)b * C_IN * NTOK;
    const float* ob = (s == 0 ? ob0 : ob1);
    float* oo = out + ((size_t)s * NB + b) * C_IN * NTOK;

    uint32_t sb = smem_u32(sc);
    int nb0 = tid >> 4;
    int cidx = tid & 15;
    uint32_t kdst = (uint32_t)nb0 * 256 + (uint32_t)((cidx ^ (nb0 & 7)) << 4);
    uint32_t vdst = 32768u + kdst;
    const char* ksrc = (const char*)Kh + (size_t)nb0 * 256 + cidx * 16;
    const char* vsrc = (const char*)Vh + (size_t)nb0 * NTOK * 2 + cidx * 16;
#pragma unroll
    for (int u = 0; u < 8; u++) {
        CP16(sb + kdst + u * 4096, ksrc + (size_t)u * 16 * 256);
        CP16(sb + vdst + u * 4096, vsrc + (size_t)u * 16 * NTOK * 2);
    }
    CP_COMMIT();

    uint32_t aq[8][4];
    {
        const uint32_t* q0p = (const uint32_t*)(Qh + (size_t)(m0 + 16 * w + g) * HID);
        const uint32_t* q1p = (const uint32_t*)(Qh + (size_t)(m0 + 16 * w + g + 8) * HID);
#pragma unroll
        for (int ks = 0; ks < 8; ks++) {
            aq[ks][0] = q0p[8 * ks + j];
            aq[ks][1] = q1p[8 * ks + j];
            aq[ks][2] = q0p[8 * ks + j + 4];
            aq[ks][3] = q1p[8 * ks + j + 4];
        }
    }

    float oacc[16][4] = {};
    float psum0 = 0.f, psum1 = 0.f;

    for (int t = 0; t < 18; t++) {
        const char* cb = sc + (size_t)(t & 1) * 65536;
        if (t + 1 < 18) {
            uint32_t nbuf = sb + (uint32_t)((t + 1) & 1) * 65536;
            const char* ks2 = ksrc + (size_t)(t + 1) * 128 * 256;
            const char* vs2 = vsrc + (size_t)(t + 1) * 256;
#pragma unroll
            for (int u = 0; u < 8; u++) {
                CP16(nbuf + kdst + u * 4096, ks2 + (size_t)u * 16 * 256);
                CP16(nbuf + vdst + u * 4096, vs2 + (size_t)u * 16 * NTOK * 2);
            }
            CP_COMMIT();
            CP_WAIT1();
        } else {
            const char* wsrc = (const char*)&g_w2[s][0][0];
#pragma unroll
            for (int u = 0; u < 16; u++) {
                int idx = tid + 256 * u;
                int row = idx >> 4, ch = idx & 15;
                CP16(sb + (uint32_t)row * 256 + (uint32_t)((ch ^ (row & 7)) << 4),
                     wsrc + (size_t)idx * 16);
            }
            CP_COMMIT();
            CP_WAIT1();
        }
        __syncthreads();

        float sacc[16][4] = {};
#pragma unroll
        for (int ks = 0; ks < 8; ks++) {
            uint32_t e0 = (uint32_t)(((2 * ks) ^ g) * 16 + 4 * j);
            uint32_t e1 = (uint32_t)(((2 * ks + 1) ^ g) * 16 + 4 * j);
#pragma unroll
            for (int nt = 0; nt < 16; nt++) {
                const char* kb = cb + (8 * nt + g) * 256;
                mma16(sacc[nt], aq[ks],
                      *(const uint32_t*)(kb + e0), *(const uint32_t*)(kb + e1));
            }
        }

        uint32_t ap[8][4];
#pragma unroll
        for (int k2 = 0; k2 < 8; k2++) {
            float p00 = ex2f(sacc[2 * k2][0]),     p01 = ex2f(sacc[2 * k2][1]);
            float p02 = ex2f(sacc[2 * k2][2]),     p03 = ex2f(sacc[2 * k2][3]);
            float p10 = ex2f(sacc[2 * k2 + 1][0]), p11 = ex2f(sacc[2 * k2 + 1][1]);
            float p12 = ex2f(sacc[2 * k2 + 1][2]), p13 = ex2f(sacc[2 * k2 + 1][3]);
            psum0 += p00 + p01 + p10 + p11;
            psum1 += p02 + p03 + p12 + p13;
            ap[k2][0] = packh(p00, p01);
            ap[k2][1] = packh(p02, p03);
            ap[k2][2] = packh(p10, p11);
            ap[k2][3] = packh(p12, p13);
        }

        const char* vfp = cb + 32768;
#pragma unroll
        for (int k2 = 0; k2 < 8; k2++) {
            uint32_t e0 = (uint32_t)(((2 * k2) ^ g) * 16 + 4 * j);
            uint32_t e1 = (uint32_t)(((2 * k2 + 1) ^ g) * 16 + 4 * j);
#pragma unroll
            for (int dt = 0; dt < 16; dt++) {
                const char* vb = vfp + (8 * dt + g) * 256;
                mma16(oacc[dt], ap[k2],
                      *(const uint32_t*)(vb + e0), *(const uint32_t*)(vb + e1));
            }
        }
        __syncthreads();
    }

    CP_WAIT0();
    __syncthreads();

    psum0 += __shfl_xor_sync(0xffffffffu, psum0, 1);
    psum0 += __shfl_xor_sync(0xffffffffu, psum0, 2);
    psum1 += __shfl_xor_sync(0xffffffffu, psum1, 1);
    psum1 += __shfl_xor_sync(0xffffffffu, psum1, 2);
    float inv0 = 1.f / psum0, inv1 = 1.f / psum1;

    uint32_t bp0[8][2], bp1[8][2];
#pragma unroll
    for (int kk = 0; kk < 8; kk++) {
        bp0[kk][0] = packh(oacc[2 * kk][0] * inv0,     oacc[2 * kk][1] * inv0);
        bp0[kk][1] = packh(oacc[2 * kk + 1][0] * inv0, oacc[2 * kk + 1][1] * inv0);
        bp1[kk][0] = packh(oacc[2 * kk][2] * inv1,     oacc[2 * kk][3] * inv1);
        bp1[kk][1] = packh(oacc[2 * kk + 1][2] * inv1, oacc[2 * kk + 1][3] * inv1);
    }

    const uint32_t* w32 = (const uint32_t*)sc;
#pragma unroll
    for (int ot = 0; ot < 16; ot++) {
        float ac0[4] = {}, ac1[4] = {};
        int r0 = (16 * ot + g) * 64, r1 = (16 * ot + 8 + g) * 64;
#pragma unroll
        for (int kk = 0; kk < 8; kk++) {
            uint32_t a[4];
            int e0 = (8 * kk + j) ^ (4 * g);
            int e1 = (8 * kk + 4 + j) ^ (4 * g);
            a[0] = w32[r0 + e0];
            a[1] = w32[r1 + e0];
            a[2] = w32[r0 + e1];
            a[3] = w32[r1 + e1];
            mma16(ac0, a, bp0[kk][0], bp0[kk][1]);
            mma16(ac1, a, bp1[kk][0], bp1[kk][1]);
        }
        int oa = 16 * ot + g, obr = oa + 8;
        float ba = ob[oa], bb = ob[obr];
        int mA = m0 + 16 * w + 2 * j;
        const float* xr0 = x + (size_t)oa * NTOK + mA;
        const float* xr1 = x + (size_t)obr * NTOK + mA;
        float* or0 = oo + (size_t)oa * NTOK + mA;
        float* or1 = oo + (size_t)obr * NTOK + mA;
        float2 q00 = *(const float2*)xr0, q01 = *(const float2*)(xr0 + 8);
        float2 q10 = *(const float2*)xr1, q11 = *(const float2*)(xr1 + 8);
        *(float2*)or0       = make_float2(ac0[0] + ba + q00.x, ac0[1] + ba + q00.y);
        *(float2*)(or0 + 8) = make_float2(ac1[0] + ba + q01.x, ac1[1] + ba + q01.y);
        *(float2*)or1       = make_float2(ac0[2] + bb + q10.x, ac0[3] + bb + q10.y);
        *(float2*)(or1 + 8) = make_float2(ac1[2] + bb + q11.x, ac1[3] + bb + q11.y);
    }
}

// ---------------- launch ----------------
extern "C" void kernel_launch(void* const* d_in, const int* in_sizes, int n_in,
                              void* d_out, int out_size) {
    const float* x0  = (const float*)d_in[0];
    const float* x1  = (const float*)d_in[1];
    const float* ew0 = (const float*)d_in[2];
    const float* eb0 = (const float*)d_in[3];
    const float* ew1 = (const float*)d_in[4];
    const float* eb1 = (const float*)d_in[5];
    const float* ow0 = (const float*)d_in[6];
    const float* ob0 = (const float*)d_in[7];
    const float* ow1 = (const float*)d_in[8];
    const float* ob1 = (const float*)d_in[9];
    float* out = (float*)d_out;

    wh_kernel<<<dim3(384, NSTREAMS), 128>>>(ew0, ew1);
    weff_kernel<<<dim3(HID / 2, NSTREAMS), C_IN>>>(ow0, ow1);

    int smem_e = 9216 + 3 * 16384;   // 58368
    cudaFuncSetAttribute(embed_kernel, cudaFuncAttributeMaxDynamicSharedMemorySize, smem_e);
    embed_kernel<<<dim3(NTOK / 64, 16), 256, smem_e>>>(x0, x1, eb0, eb1);

    int smem_a = 2 * 65536;
    cudaFuncSetAttribute(attn_kernel, cudaFuncAttributeMaxDynamicSharedMemorySize, smem_a);
    attn_kernel<<<dim3(NTOK / 128, NB, NSTREAMS), 256, smem_a>>>(x0, x1, ob0, ob1, out);
}

// round 14
// speedup vs baseline: 13.3558x; 1.0131x over previous
#include <cuda_runtime.h>
#include <cuda_fp16.h>
#include <cstdint>

#define NSTREAMS 2
#define NB 8
#define C_IN 256
#define HID 128
#define NTOK 2304
#define QSCL 0.09016844005f   // 256^-0.5 * log2(e), folded into q (via wh rows o<128)

// ---------------- scratch (device globals; no allocs allowed) ----------------
__device__ __half   g_qh[NSTREAMS][NB][NTOK][HID];  // token-major, scaled, fp16
__device__ __half   g_kh[NSTREAMS][NB][NTOK][HID];  // token-major, fp16
__device__ __half   g_vh[NSTREAMS][NB][HID][NTOK];  // channel-major, fp16
__device__ uint32_t g_w2[NSTREAMS][C_IN][HID / 2];  // W_eff [o][c2] half2 (c even lo)
__device__ uint32_t g_wh[NSTREAMS][384][C_IN / 2];  // embed W fp16 pairs [o][c2]

// ---------------- helpers ----------------
__device__ __forceinline__ float ex2f(float x) {
    float y; asm("ex2.approx.ftz.f32 %0, %1;" : "=f"(y) : "f"(x)); return y;
}
__device__ __forceinline__ uint32_t packh(float lo, float hi) {
    uint32_t d; asm("cvt.rn.f16x2.f32 %0, %1, %2;" : "=r"(d) : "f"(hi), "f"(lo));
    return d;
}
__device__ __forceinline__ void mma16(float c[4], const uint32_t a[4],
                                      uint32_t b0, uint32_t b1) {
    asm volatile(
        "mma.sync.aligned.m16n8k16.row.col.f32.f16.f16.f32 "
        "{%0,%1,%2,%3}, {%4,%5,%6,%7}, {%8,%9}, {%0,%1,%2,%3};"
        : "+f"(c[0]), "+f"(c[1]), "+f"(c[2]), "+f"(c[3])
        : "r"(a[0]), "r"(a[1]), "r"(a[2]), "r"(a[3]), "r"(b0), "r"(b1));
}
__device__ __forceinline__ uint32_t smem_u32(const void* p) {
    uint32_t a;
    asm("{ .reg .u64 t; cvta.to.shared.u64 t, %1; cvt.u32.u64 %0, t; }" : "=r"(a) : "l"(p));
    return a;
}
#define CP16(dst, src) asm volatile("cp.async.cg.shared.global [%0], [%1], 16;" :: "r"(dst), "l"(src))
#define CP_COMMIT()    asm volatile("cp.async.commit_group;" ::: "memory")
#define CP_WAIT1()     asm volatile("cp.async.wait_group 1;" ::: "memory")
#define CP_WAIT0()     asm volatile("cp.async.wait_group 0;" ::: "memory")

// ---------------- pre-convert embed weight to fp16 pairs (QSCL folded for q) ----------------
__global__ void wh_kernel(const float* __restrict__ w0, const float* __restrict__ w1) {
    int o = blockIdx.x;            // 0..383
    int s = blockIdx.y;
    const float* w = (s == 0 ? w0 : w1) + (size_t)o * C_IN;
    float scl = (o < HID) ? QSCL : 1.0f;
    int c2 = threadIdx.x;          // 0..127
    g_wh[s][o][c2] = packh(w[2 * c2] * scl, w[2 * c2 + 1] * scl);
}

// =======================================================================
// embed (fp16 mma): one CTA computes q,k,v for a 64-token m-tile.
// =======================================================================
__global__ void __launch_bounds__(256, 2) embed_kernel(
        const float* __restrict__ x0, const float* __restrict__ x1,
        const float* __restrict__ b0_, const float* __restrict__ b1_) {
    extern __shared__ char esm[];
    uint32_t* sX = (uint32_t*)esm;          // [32 c2][72 pad] half2 words
    char* wsm = esm + 9216;                 // 3 oy x 16384 B, chunk-XOR swizzled
    float* sT = (float*)(esm + 9216);       // [128 d][66 m] transpose overlay

    int z = blockIdx.y;
    int s = z >> 3, b = z & 7;
    const float* x = (s == 0 ? x0 : x1) + (size_t)b * C_IN * NTOK;
    const float* bias = (s == 0 ? b0_ : b1_);
    const uint32_t* wh = &g_wh[s][0][0];
    int m0 = blockIdx.x * 64;
    int tid = threadIdx.x;
    int l = tid & 31, wq = tid >> 5;
    int g = l >> 2, j = l & 3;
    uint32_t sb = smem_u32(esm);

    float acc[3][8][4] = {};

    for (int c = 0; c < 4; c++) {
        int k0 = 64 * c;
#pragma unroll
        for (int u = 0; u < 12; u++) {
            int idx = tid + 256 * u;
            int oyi = idx >> 10, rem = idx & 1023;
            int row = rem >> 3, ch = rem & 7;
            uint32_t dst = sb + 9216u + (uint32_t)oyi * 16384u
                         + (uint32_t)row * 128u + (uint32_t)((ch ^ (row & 7)) << 4);
            const char* src = (const char*)(wh + (size_t)(oyi * 128 + row) * 128
                                            + (k0 >> 1) + ch * 4);
            CP16(dst, src);
        }
        CP_COMMIT();
#pragma unroll
        for (int u = 0; u < 2; u++) {
            int idx = tid + 256 * u;
            int k2 = idx >> 4, m4 = idx & 15;
            const float* xa = x + (size_t)(k0 + 2 * k2) * NTOK + m0 + 4 * m4;
            float4 fa = *(const float4*)xa;
            float4 fb = *(const float4*)(xa + NTOK);
            uint4 p;
            p.x = packh(fa.x, fb.x); p.y = packh(fa.y, fb.y);
            p.z = packh(fa.z, fb.z); p.w = packh(fa.w, fb.w);
            *(uint4*)(sX + k2 * 72 + 4 * m4) = p;
        }
        CP_WAIT0();
        __syncthreads();
#pragma unroll
        for (int oy = 0; oy < 3; oy++) {
            const char* wrow0 = wsm + oy * 16384 + (16 * wq + g) * 128;
            const char* wrow1 = wrow0 + 8 * 128;
#pragma unroll
            for (int ks = 0; ks < 4; ks++) {
                int e0 = ((2 * ks) ^ g) * 16 + 4 * j;
                int e1 = ((2 * ks + 1) ^ g) * 16 + 4 * j;
                uint32_t a[4];
                a[0] = *(const uint32_t*)(wrow0 + e0);
                a[1] = *(const uint32_t*)(wrow1 + e0);
                a[2] = *(const uint32_t*)(wrow0 + e1);
                a[3] = *(const uint32_t*)(wrow1 + e1);
                const uint32_t* xb0 = sX + (8 * ks + j) * 72 + g;
                const uint32_t* xb1 = sX + (8 * ks + 4 + j) * 72 + g;
#pragma unroll
                for (int nt = 0; nt < 8; nt++)
                    mma16(acc[oy][nt], a, xb0[8 * nt], xb1[8 * nt]);
            }
        }
        __syncthreads();
    }

    {   // v epilogue
        int d0 = 16 * wq + g, d1 = d0 + 8;
        float bv0 = bias[256 + d0], bv1 = bias[256 + d1];
        __half* v0 = &g_vh[s][b][d0][0];
        __half* v1 = &g_vh[s][b][d1][0];
#pragma unroll
        for (int nt = 0; nt < 8; nt++) {
            int m = m0 + 8 * nt + 2 * j;
            *(__half2*)(v0 + m) = __floats2half2_rn(acc[2][nt][0] + bv0, acc[2][nt][1] + bv0);
            *(__half2*)(v1 + m) = __floats2half2_rn(acc[2][nt][2] + bv1, acc[2][nt][3] + bv1);
        }
    }
#pragma unroll
    for (int oy = 0; oy < 2; oy++) {   // q/k transpose epilogue
        __syncthreads();
        int d0 = 16 * wq + g, d1 = d0 + 8;
#pragma unroll
        for (int nt = 0; nt < 8; nt++) {
            int m = 8 * nt + 2 * j;
            *(float2*)(sT + d0 * 66 + m) = make_float2(acc[oy][nt][0], acc[oy][nt][1]);
            *(float2*)(sT + d1 * 66 + m) = make_float2(acc[oy][nt][2], acc[oy][nt][3]);
        }
        __syncthreads();
        float bscl = (oy == 0) ? QSCL : 1.0f;
        __half* base = (oy == 0) ? &g_qh[s][b][0][0] : &g_kh[s][b][0][0];
        float bv[4];
#pragma unroll
        for (int k = 0; k < 4; k++) bv[k] = bias[oy * 128 + l + 32 * k] * bscl;
        for (int mrow = wq; mrow < 64; mrow += 8) {
            __half* dst = base + (size_t)(m0 + mrow) * HID;
#pragma unroll
            for (int k = 0; k < 4; k++) {
                int d = l + 32 * k;
                dst[d] = __float2half_rn(sT[d * 66 + mrow] + bv[k]);
            }
        }
    }
}

// ---------------- head-fold output weight -> fp16 pairs [o][c2] ----------------
__global__ void weff_kernel(const float* __restrict__ w0, const float* __restrict__ w1) {
    int k2 = blockIdx.x;
    int s = blockIdx.y;
    int o = threadIdx.x;
    const float* w = (s == 0 ? w0 : w1);
    float e = 0.f, d = 0.f;
#pragma unroll
    for (int h = 0; h < 4; h++) {
        e += w[(size_t)(2 * k2 + HID * h) * C_IN + o];
        d += w[(size_t)(2 * k2 + 1 + HID * h) * C_IN + o];
    }
    g_w2[s][o][k2] = packh(e, d);
}

// =======================================================================
// attention + fused output projection. Warp M-tile = 32 queries,
// CTA = 256 queries, grid = 144 CTAs (one wave). 16-key softmax groups.
// =======================================================================
__global__ void __launch_bounds__(256, 1) attn_kernel(
        const float* __restrict__ x0, const float* __restrict__ x1,
        const float* __restrict__ ob0, const float* __restrict__ ob1,
        float* __restrict__ out) {
    extern __shared__ char sc[];   // [2][65536]: kf at +0, vf at +32768 per buffer

    int tid = threadIdx.x;
    int l = tid & 31, w = tid >> 5;
    int g = l >> 2, j = l & 3;
    int m0 = blockIdx.x * 256;
    int b = blockIdx.y, s = blockIdx.z;
    const __half* Qh = &g_qh[1 - s][b][0][0];
    const __half* Kh = &g_kh[s][b][0][0];
    const __half* Vh = &g_vh[s][b][0][0];
    const float* x = (s == 0 ? x0 : x1) + (size_t)b * C_IN * NTOK;
    const float* ob = (s == 0 ? ob0 : ob1);
    float* oo = out + ((size_t)s * NB + b) * C_IN * NTOK;

    // ---- cp.async prefetch tile 0 ----
    uint32_t sb = smem_u32(sc);
    int nb0 = tid >> 4;
    int cidx = tid & 15;
    uint32_t kdst = (uint32_t)nb0 * 256 + (uint32_t)((cidx ^ (nb0 & 7)) << 4);
    uint32_t vdst = 32768u + kdst;
    const char* ksrc = (const char*)Kh + (size_t)nb0 * 256 + cidx * 16;
    const char* vsrc = (const char*)Vh + (size_t)nb0 * NTOK * 2 + cidx * 16;
#pragma unroll
    for (int u = 0; u < 8; u++) {
        CP16(sb + kdst + u * 4096, ksrc + (size_t)u * 16 * 256);
        CP16(sb + vdst + u * 4096, vsrc + (size_t)u * 16 * NTOK * 2);
    }
    CP_COMMIT();

    // ---- Q fragments -> registers (32 query rows per warp) ----
    int q0 = m0 + 32 * w;
    uint32_t aqa[8][4], aqb[8][4];
    {
        const uint32_t* p0 = (const uint32_t*)(Qh + (size_t)(q0 + g) * HID);
        const uint32_t* p1 = (const uint32_t*)(Qh + (size_t)(q0 + 8 + g) * HID);
        const uint32_t* p2 = (const uint32_t*)(Qh + (size_t)(q0 + 16 + g) * HID);
        const uint32_t* p3 = (const uint32_t*)(Qh + (size_t)(q0 + 24 + g) * HID);
#pragma unroll
        for (int ks = 0; ks < 8; ks++) {
            aqa[ks][0] = p0[8 * ks + j];
            aqa[ks][1] = p1[8 * ks + j];
            aqa[ks][2] = p0[8 * ks + j + 4];
            aqa[ks][3] = p1[8 * ks + j + 4];
            aqb[ks][0] = p2[8 * ks + j];
            aqb[ks][1] = p3[8 * ks + j];
            aqb[ks][2] = p2[8 * ks + j + 4];
            aqb[ks][3] = p3[8 * ks + j + 4];
        }
    }

    float oA[16][4] = {}, oB[16][4] = {};
    float psA0 = 0.f, psA1 = 0.f, psB0 = 0.f, psB1 = 0.f;

    for (int t = 0; t < 18; t++) {
        const char* cb = sc + (size_t)(t & 1) * 65536;
        if (t + 1 < 18) {
            uint32_t nbuf = sb + (uint32_t)((t + 1) & 1) * 65536;
            const char* ks2 = ksrc + (size_t)(t + 1) * 128 * 256;
            const char* vs2 = vsrc + (size_t)(t + 1) * 256;
#pragma unroll
            for (int u = 0; u < 8; u++) {
                CP16(nbuf + kdst + u * 4096, ks2 + (size_t)u * 16 * 256);
                CP16(nbuf + vdst + u * 4096, vs2 + (size_t)u * 16 * NTOK * 2);
            }
            CP_COMMIT();
            CP_WAIT1();
        } else {
            const char* wsrc = (const char*)&g_w2[s][0][0];
#pragma unroll
            for (int u = 0; u < 16; u++) {
                int idx = tid + 256 * u;
                int row = idx >> 4, ch = idx & 15;
                CP16(sb + (uint32_t)row * 256 + (uint32_t)((ch ^ (row & 7)) << 4),
                     wsrc + (size_t)idx * 16);
            }
            CP_COMMIT();
            CP_WAIT1();
        }
        __syncthreads();

        const char* kf = cb;
        const char* vf = cb + 32768;

        // ---- 8 groups of 16 keys: S-mma -> exp -> PV-mma ----
#pragma unroll
        for (int ntg = 0; ntg < 8; ntg++) {
            float s00[4] = {}, s01[4] = {}, s10[4] = {}, s11[4] = {};
            const char* kr0 = kf + (16 * ntg + g) * 256;
            const char* kr1 = kr0 + 8 * 256;
#pragma unroll
            for (int ks = 0; ks < 8; ks++) {
                int e0 = ((2 * ks) ^ g) * 16 + 4 * j;
                int e1 = ((2 * ks + 1) ^ g) * 16 + 4 * j;
                uint32_t b00 = *(const uint32_t*)(kr0 + e0);
                uint32_t b01 = *(const uint32_t*)(kr0 + e1);
                uint32_t b10 = *(const uint32_t*)(kr1 + e0);
                uint32_t b11 = *(const uint32_t*)(kr1 + e1);
                mma16(s00, aqa[ks], b00, b01);
                mma16(s01, aqb[ks], b00, b01);
                mma16(s10, aqa[ks], b10, b11);
                mma16(s11, aqb[ks], b10, b11);
            }
            // exp2 + row sums + pack A fragments for PV
            float a0 = ex2f(s00[0]), a1 = ex2f(s00[1]), a2 = ex2f(s00[2]), a3 = ex2f(s00[3]);
            float a4 = ex2f(s10[0]), a5 = ex2f(s10[1]), a6 = ex2f(s10[2]), a7 = ex2f(s10[3]);
            float b0f = ex2f(s01[0]), b1f = ex2f(s01[1]), b2f = ex2f(s01[2]), b3f = ex2f(s01[3]);
            float b4f = ex2f(s11[0]), b5f = ex2f(s11[1]), b6f = ex2f(s11[2]), b7f = ex2f(s11[3]);
            psA0 += a0 + a1 + a4 + a5;
            psA1 += a2 + a3 + a6 + a7;
            psB0 += b0f + b1f + b4f + b5f;
            psB1 += b2f + b3f + b6f + b7f;
            uint32_t apA[4], apB[4];
            apA[0] = packh(a0, a1); apA[1] = packh(a2, a3);
            apA[2] = packh(a4, a5); apA[3] = packh(a6, a7);
            apB[0] = packh(b0f, b1f); apB[1] = packh(b2f, b3f);
            apB[2] = packh(b4f, b5f); apB[3] = packh(b6f, b7f);

            int e0v = ((2 * ntg) ^ g) * 16 + 4 * j;
            int e1v = ((2 * ntg + 1) ^ g) * 16 + 4 * j;
#pragma unroll
            for (int dt = 0; dt < 16; dt++) {
                const char* vb = vf + (8 * dt + g) * 256;
                uint32_t v0 = *(const uint32_t*)(vb + e0v);
                uint32_t v1 = *(const uint32_t*)(vb + e1v);
                mma16(oA[dt], apA, v0, v1);
                mma16(oB[dt], apB, v0, v1);
            }
        }
        __syncthreads();
    }

    // ---- W_eff arrived ----
    CP_WAIT0();
    __syncthreads();

    // ---- row-sum reduce + pack O into out-GEMM B fragments ----
    psA0 += __shfl_xor_sync(0xffffffffu, psA0, 1);
    psA0 += __shfl_xor_sync(0xffffffffu, psA0, 2);
    psA1 += __shfl_xor_sync(0xffffffffu, psA1, 1);
    psA1 += __shfl_xor_sync(0xffffffffu, psA1, 2);
    psB0 += __shfl_xor_sync(0xffffffffu, psB0, 1);
    psB0 += __shfl_xor_sync(0xffffffffu, psB0, 2);
    psB1 += __shfl_xor_sync(0xffffffffu, psB1, 1);
    psB1 += __shfl_xor_sync(0xffffffffu, psB1, 2);
    float iA0 = 1.f / psA0, iA1 = 1.f / psA1;
    float iB0 = 1.f / psB0, iB1 = 1.f / psB1;

    uint32_t bp0[8][2], bp1[8][2], bp2[8][2], bp3[8][2];
#pragma unroll
    for (int kk = 0; kk < 8; kk++) {
        bp0[kk][0] = packh(oA[2 * kk][0] * iA0,     oA[2 * kk][1] * iA0);
        bp0[kk][1] = packh(oA[2 * kk + 1][0] * iA0, oA[2 * kk + 1][1] * iA0);
        bp1[kk][0] = packh(oA[2 * kk][2] * iA1,     oA[2 * kk][3] * iA1);
        bp1[kk][1] = packh(oA[2 * kk + 1][2] * iA1, oA[2 * kk + 1][3] * iA1);
        bp2[kk][0] = packh(oB[2 * kk][0] * iB0,     oB[2 * kk][1] * iB0);
        bp2[kk][1] = packh(oB[2 * kk + 1][0] * iB0, oB[2 * kk + 1][1] * iB0);
        bp3[kk][0] = packh(oB[2 * kk][2] * iB1,     oB[2 * kk][3] * iB1);
        bp3[kk][1] = packh(oB[2 * kk + 1][2] * iB1, oB[2 * kk + 1][3] * iB1);
    }

    // ---- Out[o][m] = Weff H + bias + x : A = Weff (SMEM), B = bp (regs) ----
    const uint32_t* w32 = (const uint32_t*)sc;
#pragma unroll
    for (int ot = 0; ot < 16; ot++) {
        float ac0[4] = {}, ac1[4] = {}, ac2[4] = {}, ac3[4] = {};
        int r0 = (16 * ot + g) * 64, r1 = (16 * ot + 8 + g) * 64;
#pragma unroll
        for (int kk = 0; kk < 8; kk++) {
            uint32_t a[4];
            int e0 = (8 * kk + j) ^ (4 * g);
            int e1 = (8 * kk + 4 + j) ^ (4 * g);
            a[0] = w32[r0 + e0];
            a[1] = w32[r1 + e0];
            a[2] = w32[r0 + e1];
            a[3] = w32[r1 + e1];
            mma16(ac0, a, bp0[kk][0], bp0[kk][1]);
            mma16(ac1, a, bp1[kk][0], bp1[kk][1]);
            mma16(ac2, a, bp2[kk][0], bp2[kk][1]);
            mma16(ac3, a, bp3[kk][0], bp3[kk][1]);
        }
        int oa = 16 * ot + g, obr = oa + 8;
        float ba = ob[oa], bb = ob[obr];
        int mA = q0 + 2 * j;
        const float* xr0 = x + (size_t)oa * NTOK + mA;
        const float* xr1 = x + (size_t)obr * NTOK + mA;
        float* or0 = oo + (size_t)oa * NTOK + mA;
        float* or1 = oo + (size_t)obr * NTOK + mA;
        float2 xv;
        xv = *(const float2*)xr0;
        *(float2*)or0 = make_float2(ac0[0] + ba + xv.x, ac0[1] + ba + xv.y);
        xv = *(const float2*)(xr0 + 8);
        *(float2*)(or0 + 8) = make_float2(ac1[0] + ba + xv.x, ac1[1] + ba + xv.y);
        xv = *(const float2*)(xr0 + 16);
        *(float2*)(or0 + 16) = make_float2(ac2[0] + ba + xv.x, ac2[1] + ba + xv.y);
        xv = *(const float2*)(xr0 + 24);
        *(float2*)(or0 + 24) = make_float2(ac3[0] + ba + xv.x, ac3[1] + ba + xv.y);
        xv = *(const float2*)xr1;
        *(float2*)or1 = make_float2(ac0[2] + bb + xv.x, ac0[3] + bb + xv.y);
        xv = *(const float2*)(xr1 + 8);
        *(float2*)(or1 + 8) = make_float2(ac1[2] + bb + xv.x, ac1[3] + bb + xv.y);
        xv = *(const float2*)(xr1 + 16);
        *(float2*)(or1 + 16) = make_float2(ac2[2] + bb + xv.x, ac2[3] + bb + xv.y);
        xv = *(const float2*)(xr1 + 24);
        *(float2*)(or1 + 24) = make_float2(ac3[2] + bb + xv.x, ac3[3] + bb + xv.y);
    }
}

// ---------------- launch ----------------
extern "C" void kernel_launch(void* const* d_in, const int* in_sizes, int n_in,
                              void* d_out, int out_size) {
    const float* x0  = (const float*)d_in[0];
    const float* x1  = (const float*)d_in[1];
    const float* ew0 = (const float*)d_in[2];
    const float* eb0 = (const float*)d_in[3];
    const float* ew1 = (const float*)d_in[4];
    const float* eb1 = (const float*)d_in[5];
    const float* ow0 = (const float*)d_in[6];
    const float* ob0 = (const float*)d_in[7];
    const float* ow1 = (const float*)d_in[8];
    const float* ob1 = (const float*)d_in[9];
    float* out = (float*)d_out;

    wh_kernel<<<dim3(384, NSTREAMS), 128>>>(ew0, ew1);
    weff_kernel<<<dim3(HID / 2, NSTREAMS), C_IN>>>(ow0, ow1);

    int smem_e = 9216 + 3 * 16384;   // 58368
    cudaFuncSetAttribute(embed_kernel, cudaFuncAttributeMaxDynamicSharedMemorySize, smem_e);
    embed_kernel<<<dim3(NTOK / 64, 16), 256, smem_e>>>(x0, x1, eb0, eb1);

    int smem_a = 2 * 65536;
    cudaFuncSetAttribute(attn_kernel, cudaFuncAttributeMaxDynamicSharedMemorySize, smem_a);
    attn_kernel<<<dim3(NTOK / 256, NB, NSTREAMS), 256, smem_a>>>(x0, x1, ob0, ob1, out);
}

// round 15
// speedup vs baseline: 13.5013x; 1.0109x over previous
#include <cuda_runtime.h>
#include <cuda_fp16.h>
#include <cstdint>

#define NSTREAMS 2
#define NB 8
#define C_IN 256
#define HID 128
#define NTOK 2304
#define QSCL 0.09016844005f   // 256^-0.5 * log2(e), folded into q (via wh rows o<128)

// ---------------- scratch (device globals; no allocs allowed) ----------------
// NOTE: g_qh/g_kh rows use a PERMUTED d-order; g_vh rows use the same permutation
// on n within each 128-token block:  val(16k+8h+2j+b) stored at byte 32k+8j+4h+2b.
__device__ __half   g_qh[NSTREAMS][NB][NTOK][HID];
__device__ __half   g_kh[NSTREAMS][NB][NTOK][HID];
__device__ __half   g_vh[NSTREAMS][NB][HID][NTOK];
__device__ uint32_t g_w2[NSTREAMS][C_IN][HID / 2];  // W_eff [o][c2] half2 (c even lo)
__device__ uint32_t g_wh[NSTREAMS][384][C_IN / 2];  // embed W fp16 pairs [o][c2]

// ---------------- helpers ----------------
__device__ __forceinline__ float ex2f(float x) {
    float y; asm("ex2.approx.ftz.f32 %0, %1;" : "=f"(y) : "f"(x)); return y;
}
__device__ __forceinline__ uint32_t packh(float lo, float hi) {
    uint32_t d; asm("cvt.rn.f16x2.f32 %0, %1, %2;" : "=r"(d) : "f"(hi), "f"(lo));
    return d;
}
__device__ __forceinline__ void mma16(float c[4], const uint32_t a[4],
                                      uint32_t b0, uint32_t b1) {
    asm volatile(
        "mma.sync.aligned.m16n8k16.row.col.f32.f16.f16.f32 "
        "{%0,%1,%2,%3}, {%4,%5,%6,%7}, {%8,%9}, {%0,%1,%2,%3};"
        : "+f"(c[0]), "+f"(c[1]), "+f"(c[2]), "+f"(c[3])
        : "r"(a[0]), "r"(a[1]), "r"(a[2]), "r"(a[3]), "r"(b0), "r"(b1));
}
__device__ __forceinline__ uint32_t smem_u32(const void* p) {
    uint32_t a;
    asm("{ .reg .u64 t; cvta.to.shared.u64 t, %1; cvt.u32.u64 %0, t; }" : "=r"(a) : "l"(p));
    return a;
}
// in-row permutation: value index v (0..127) -> byte offset (0..255)
__device__ __forceinline__ int permb(int v) {
    int ks = v >> 4, r = v & 15;
    return 32 * ks + 8 * ((r >> 1) & 3) + 4 * (r >> 3) + 2 * (v & 1);
}
#define CP16(dst, src) asm volatile("cp.async.cg.shared.global [%0], [%1], 16;" :: "r"(dst), "l"(src))
#define CP_COMMIT()    asm volatile("cp.async.commit_group;" ::: "memory")
#define CP_WAIT1()     asm volatile("cp.async.wait_group 1;" ::: "memory")
#define CP_WAIT0()     asm volatile("cp.async.wait_group 0;" ::: "memory")

// ---------------- pre-convert embed weight to fp16 pairs (QSCL folded for q) ----------------
__global__ void wh_kernel(const float* __restrict__ w0, const float* __restrict__ w1) {
    int o = blockIdx.x;
    int s = blockIdx.y;
    const float* w = (s == 0 ? w0 : w1) + (size_t)o * C_IN;
    float scl = (o < HID) ? QSCL : 1.0f;
    int c2 = threadIdx.x;
    g_wh[s][o][c2] = packh(w[2 * c2] * scl, w[2 * c2 + 1] * scl);
}

// =======================================================================
// embed (fp16 mma): one CTA computes q,k,v for a 64-token m-tile.
// Outputs written in the attn-fragment permuted order (see permb).
// =======================================================================
__global__ void __launch_bounds__(256, 2) embed_kernel(
        const float* __restrict__ x0, const float* __restrict__ x1,
        const float* __restrict__ b0_, const float* __restrict__ b1_) {
    extern __shared__ char esm[];
    uint32_t* sX = (uint32_t*)esm;          // [32 c2][72 pad] half2 words
    char* wsm = esm + 9216;                 // 3 oy x 16384 B, chunk-XOR swizzled
    float* sT = (float*)(esm + 9216);       // [128 d][66 m] transpose overlay

    int z = blockIdx.y;
    int s = z >> 3, b = z & 7;
    const float* x = (s == 0 ? x0 : x1) + (size_t)b * C_IN * NTOK;
    const float* bias = (s == 0 ? b0_ : b1_);
    const uint32_t* wh = &g_wh[s][0][0];
    int m0 = blockIdx.x * 64;
    int tid = threadIdx.x;
    int l = tid & 31, wq = tid >> 5;
    int g = l >> 2, j = l & 3;
    uint32_t sb = smem_u32(esm);

    float acc[3][8][4] = {};

    for (int c = 0; c < 4; c++) {
        int k0 = 64 * c;
#pragma unroll
        for (int u = 0; u < 12; u++) {
            int idx = tid + 256 * u;
            int oyi = idx >> 10, rem = idx & 1023;
            int row = rem >> 3, ch = rem & 7;
            uint32_t dst = sb + 9216u + (uint32_t)oyi * 16384u
                         + (uint32_t)row * 128u + (uint32_t)((ch ^ (row & 7)) << 4);
            const char* src = (const char*)(wh + (size_t)(oyi * 128 + row) * 128
                                            + (k0 >> 1) + ch * 4);
            CP16(dst, src);
        }
        CP_COMMIT();
#pragma unroll
        for (int u = 0; u < 2; u++) {
            int idx = tid + 256 * u;
            int k2 = idx >> 4, m4 = idx & 15;
            const float* xa = x + (size_t)(k0 + 2 * k2) * NTOK + m0 + 4 * m4;
            float4 fa = *(const float4*)xa;
            float4 fb = *(const float4*)(xa + NTOK);
            uint4 p;
            p.x = packh(fa.x, fb.x); p.y = packh(fa.y, fb.y);
            p.z = packh(fa.z, fb.z); p.w = packh(fa.w, fb.w);
            *(uint4*)(sX + k2 * 72 + 4 * m4) = p;
        }
        CP_WAIT0();
        __syncthreads();
#pragma unroll
        for (int oy = 0; oy < 3; oy++) {
            const char* wrow0 = wsm + oy * 16384 + (16 * wq + g) * 128;
            const char* wrow1 = wrow0 + 8 * 128;
#pragma unroll
            for (int ks = 0; ks < 4; ks++) {
                int e0 = ((2 * ks) ^ g) * 16 + 4 * j;
                int e1 = ((2 * ks + 1) ^ g) * 16 + 4 * j;
                uint32_t a[4];
                a[0] = *(const uint32_t*)(wrow0 + e0);
                a[1] = *(const uint32_t*)(wrow1 + e0);
                a[2] = *(const uint32_t*)(wrow0 + e1);
                a[3] = *(const uint32_t*)(wrow1 + e1);
                const uint32_t* xb0 = sX + (8 * ks + j) * 72 + g;
                const uint32_t* xb1 = sX + (8 * ks + 4 + j) * 72 + g;
#pragma unroll
                for (int nt = 0; nt < 8; nt++)
                    mma16(acc[oy][nt], a, xb0[8 * nt], xb1[8 * nt]);
            }
        }
        __syncthreads();
    }

    {   // v epilogue: channel-major rows, PERMUTED n within 128-blocks
        int d0 = 16 * wq + g, d1 = d0 + 8;
        float bv0 = bias[256 + d0], bv1 = bias[256 + d1];
        char* v0 = (char*)&g_vh[s][b][d0][0];
        char* v1 = (char*)&g_vh[s][b][d1][0];
#pragma unroll
        for (int nt = 0; nt < 8; nt++) {
            int m = m0 + 8 * nt + 2 * j;
            int off = (m & ~127) * 2 + permb(m & 127);
            *(__half2*)(v0 + off) = __floats2half2_rn(acc[2][nt][0] + bv0, acc[2][nt][1] + bv0);
            *(__half2*)(v1 + off) = __floats2half2_rn(acc[2][nt][2] + bv1, acc[2][nt][3] + bv1);
        }
    }
#pragma unroll
    for (int oy = 0; oy < 2; oy++) {   // q/k transpose epilogue, PERMUTED d
        __syncthreads();
        int d0 = 16 * wq + g, d1 = d0 + 8;
#pragma unroll
        for (int nt = 0; nt < 8; nt++) {
            int m = 8 * nt + 2 * j;
            *(float2*)(sT + d0 * 66 + m) = make_float2(acc[oy][nt][0], acc[oy][nt][1]);
            *(float2*)(sT + d1 * 66 + m) = make_float2(acc[oy][nt][2], acc[oy][nt][3]);
        }
        __syncthreads();
        float bscl = (oy == 0) ? QSCL : 1.0f;
        __half* base = (oy == 0) ? &g_qh[s][b][0][0] : &g_kh[s][b][0][0];
        float bv[4];
        int pb[4];
#pragma unroll
        for (int k = 0; k < 4; k++) {
            bv[k] = bias[oy * 128 + l + 32 * k] * bscl;
            pb[k] = permb(l + 32 * k);
        }
        for (int mrow = wq; mrow < 64; mrow += 8) {
            char* dst = (char*)(base + (size_t)(m0 + mrow) * HID);
#pragma unroll
            for (int k = 0; k < 4; k++) {
                int d = l + 32 * k;
                *(__half*)(dst + pb[k]) = __float2half_rn(sT[d * 66 + mrow] + bv[k]);
            }
        }
    }
}

// ---------------- head-fold output weight -> fp16 pairs [o][c2] ----------------
__global__ void weff_kernel(const float* __restrict__ w0, const float* __restrict__ w1) {
    int k2 = blockIdx.x;
    int s = blockIdx.y;
    int o = threadIdx.x;
    const float* w = (s == 0 ? w0 : w1);
    float e = 0.f, d = 0.f;
#pragma unroll
    for (int h = 0; h < 4; h++) {
        e += w[(size_t)(2 * k2 + HID * h) * C_IN + o];
        d += w[(size_t)(2 * k2 + 1 + HID * h) * C_IN + o];
    }
    g_w2[s][o][k2] = packh(e, d);
}

// =======================================================================
// attention + fused output projection. 8 warps x 16 queries, 16-key
// softmax groups with warp phase-stagger; LDS.64 paired B fragments.
// SMEM rows: 256B, 8B-granule swizzle g' = g ^ (4*(row&7)).
// =======================================================================
__global__ void __launch_bounds__(256, 1) attn_kernel(
        const float* __restrict__ x0, const float* __restrict__ x1,
        const float* __restrict__ ob0, const float* __restrict__ ob1,
        float* __restrict__ out) {
    extern __shared__ char sc[];   // [2][65536]: kf at +0, vf at +32768 per buffer

    int tid = threadIdx.x;
    int l = tid & 31, w = tid >> 5;
    int g = l >> 2, j = l & 3;
    int m0 = blockIdx.x * 128;
    int b = blockIdx.y, s = blockIdx.z;
    const __half* Qh = &g_qh[1 - s][b][0][0];
    const __half* Kh = &g_kh[s][b][0][0];
    const __half* Vh = &g_vh[s][b][0][0];
    const float* x = (s == 0 ? x0 : x1) + (size_t)b * C_IN * NTOK;
    const float* ob = (s == 0 ? ob0 : ob1);
    float* oo = out + ((size_t)s * NB + b) * C_IN * NTOK;

    // ---- cp.async prefetch tile 0 (chunk swizzle: ch ^ ((row&7)<<1)) ----
    uint32_t sb = smem_u32(sc);
    int nb0 = tid >> 4;
    int cidx = tid & 15;
    uint32_t kdst = (uint32_t)nb0 * 256 + (uint32_t)((cidx ^ ((nb0 & 7) << 1)) << 4);
    uint32_t vdst = 32768u + kdst;
    const char* ksrc = (const char*)Kh + (size_t)nb0 * 256 + cidx * 16;
    const char* vsrc = (const char*)Vh + (size_t)nb0 * NTOK * 2 + cidx * 16;
#pragma unroll
    for (int u = 0; u < 8; u++) {
        CP16(sb + kdst + u * 4096, ksrc + (size_t)u * 16 * 256);
        CP16(sb + vdst + u * 4096, vsrc + (size_t)u * 16 * NTOK * 2);
    }
    CP_COMMIT();

    // ---- Q fragments -> registers (permuted rows: word = 8ks + 2j + h) ----
    int q0 = m0 + 16 * w;
    uint32_t aq[8][4];
    {
        const uint32_t* p0 = (const uint32_t*)(Qh + (size_t)(q0 + g) * HID);
        const uint32_t* p1 = (const uint32_t*)(Qh + (size_t)(q0 + 8 + g) * HID);
#pragma unroll
        for (int ks = 0; ks < 8; ks++) {
            aq[ks][0] = p0[8 * ks + 2 * j];
            aq[ks][1] = p1[8 * ks + 2 * j];
            aq[ks][2] = p0[8 * ks + 2 * j + 1];
            aq[ks][3] = p1[8 * ks + 2 * j + 1];
        }
    }

    float oacc[16][4] = {};
    float psum0 = 0.f, psum1 = 0.f;
    int goff = (w >> 2) * 4;          // phase-stagger: warps 4-7 start at group 4
    uint32_t swz = (uint32_t)(4 * g); // granule XOR for this lane's rows (row&7 == g)

    for (int t = 0; t < 18; t++) {
        const char* cb = sc + (size_t)(t & 1) * 65536;
        if (t + 1 < 18) {
            uint32_t nbuf = sb + (uint32_t)((t + 1) & 1) * 65536;
            const char* ks2 = ksrc + (size_t)(t + 1) * 128 * 256;
            const char* vs2 = vsrc + (size_t)(t + 1) * 256;
#pragma unroll
            for (int u = 0; u < 8; u++) {
                CP16(nbuf + kdst + u * 4096, ks2 + (size_t)u * 16 * 256);
                CP16(nbuf + vdst + u * 4096, vs2 + (size_t)u * 16 * NTOK * 2);
            }
            CP_COMMIT();
            CP_WAIT1();
        } else {
            const char* wsrc = (const char*)&g_w2[s][0][0];
#pragma unroll
            for (int u = 0; u < 16; u++) {
                int idx = tid + 256 * u;
                int row = idx >> 4, ch = idx & 15;
                CP16(sb + (uint32_t)row * 256 + (uint32_t)((ch ^ (row & 7)) << 4),
                     wsrc + (size_t)idx * 16);
            }
            CP_COMMIT();
            CP_WAIT1();
        }
        __syncthreads();

        const char* kf = cb;
        const char* vf = cb + 32768;

        // ---- 8 staggered groups of 16 keys: S-mma -> exp -> PV-mma ----
#pragma unroll
        for (int ntg0 = 0; ntg0 < 8; ntg0++) {
            int ntg = (ntg0 + goff) & 7;
            float s0[4] = {}, s1[4] = {};
            const char* kr0 = kf + (16 * ntg + g) * 256;
            const char* kr1 = kr0 + 8 * 256;
#pragma unroll
            for (int ks = 0; ks < 8; ks++) {
                uint32_t e = ((uint32_t)(4 * ks + j) ^ swz) << 3;
                uint2 k0v = *(const uint2*)(kr0 + e);
                uint2 k1v = *(const uint2*)(kr1 + e);
                mma16(s0, aq[ks], k0v.x, k0v.y);
                mma16(s1, aq[ks], k1v.x, k1v.y);
            }
            float a0 = ex2f(s0[0]), a1 = ex2f(s0[1]), a2 = ex2f(s0[2]), a3 = ex2f(s0[3]);
            float a4 = ex2f(s1[0]), a5 = ex2f(s1[1]), a6 = ex2f(s1[2]), a7 = ex2f(s1[3]);
            psum0 += a0 + a1 + a4 + a5;
            psum1 += a2 + a3 + a6 + a7;
            uint32_t ap[4];
            ap[0] = packh(a0, a1);
            ap[1] = packh(a2, a3);
            ap[2] = packh(a4, a5);
            ap[3] = packh(a6, a7);

            uint32_t ev = ((uint32_t)(4 * ntg + j) ^ swz) << 3;
#pragma unroll
            for (int dt = 0; dt < 16; dt++) {
                uint2 vv = *(const uint2*)(vf + (8 * dt + g) * 256 + ev);
                mma16(oacc[dt], ap, vv.x, vv.y);
            }
        }
        __syncthreads();
    }

    // ---- W_eff arrived ----
    CP_WAIT0();
    __syncthreads();

    // ---- row-sum reduce + pack O into out-GEMM B fragments ----
    psum0 += __shfl_xor_sync(0xffffffffu, psum0, 1);
    psum0 += __shfl_xor_sync(0xffffffffu, psum0, 2);
    psum1 += __shfl_xor_sync(0xffffffffu, psum1, 1);
    psum1 += __shfl_xor_sync(0xffffffffu, psum1, 2);
    float inv0 = 1.f / psum0, inv1 = 1.f / psum1;

    uint32_t bp0[8][2], bp1[8][2];
#pragma unroll
    for (int kk = 0; kk < 8; kk++) {
        bp0[kk][0] = packh(oacc[2 * kk][0] * inv0,     oacc[2 * kk][1] * inv0);
        bp0[kk][1] = packh(oacc[2 * kk + 1][0] * inv0, oacc[2 * kk + 1][1] * inv0);
        bp1[kk][0] = packh(oacc[2 * kk][2] * inv1,     oacc[2 * kk][3] * inv1);
        bp1[kk][1] = packh(oacc[2 * kk + 1][2] * inv1, oacc[2 * kk + 1][3] * inv1);
    }

    // ---- Out[o][m] = Weff H + bias + x : A = Weff (SMEM), B = bp (regs) ----
    const uint32_t* w32 = (const uint32_t*)sc;
#pragma unroll
    for (int ot = 0; ot < 16; ot++) {
        float ac0[4] = {}, ac1[4] = {};
        int r0 = (16 * ot + g) * 64, r1 = (16 * ot + 8 + g) * 64;
#pragma unroll
        for (int kk = 0; kk < 8; kk++) {
            uint32_t a[4];
            int e0 = (8 * kk + j) ^ (4 * g);
            int e1 = (8 * kk + 4 + j) ^ (4 * g);
            a[0] = w32[r0 + e0];
            a[1] = w32[r1 + e0];
            a[2] = w32[r0 + e1];
            a[3] = w32[r1 + e1];
            mma16(ac0, a, bp0[kk][0], bp0[kk][1]);
            mma16(ac1, a, bp1[kk][0], bp1[kk][1]);
        }
        int oa = 16 * ot + g, obr = oa + 8;
        float ba = ob[oa], bb = ob[obr];
        int mA = q0 + 2 * j;
        const float* xr0 = x + (size_t)oa * NTOK + mA;
        const float* xr1 = x + (size_t)obr * NTOK + mA;
        float* or0 = oo + (size_t)oa * NTOK + mA;
        float* or1 = oo + (size_t)obr * NTOK + mA;
        float2 xv;
        xv = *(const float2*)xr0;
        *(float2*)or0 = make_float2(ac0[0] + ba + xv.x, ac0[1] + ba + xv.y);
        xv = *(const float2*)(xr0 + 8);
        *(float2*)(or0 + 8) = make_float2(ac1[0] + ba + xv.x, ac1[1] + ba + xv.y);
        xv = *(const float2*)xr1;
        *(float2*)or1 = make_float2(ac0[2] + bb + xv.x, ac0[3] + bb + xv.y);
        xv = *(const float2*)(xr1 + 8);
        *(float2*)(or1 + 8) = make_float2(ac1[2] + bb + xv.x, ac1[3] + bb + xv.y);
    }
}

// ---------------- launch ----------------
extern "C" void kernel_launch(void* const* d_in, const int* in_sizes, int n_in,
                              void* d_out, int out_size) {
    const float* x0  = (const float*)d_in[0];
    const float* x1  = (const float*)d_in[1];
    const float* ew0 = (const float*)d_in[2];
    const float* eb0 = (const float*)d_in[3];
    const float* ew1 = (const float*)d_in[4];
    const float* eb1 = (const float*)d_in[5];
    const float* ow0 = (const float*)d_in[6];
    const float* ob0 = (const float*)d_in[7];
    const float* ow1 = (const float*)d_in[8];
    const float* ob1 = (const float*)d_in[9];
    float* out = (float*)d_out;

    wh_kernel<<<dim3(384, NSTREAMS), 128>>>(ew0, ew1);
    weff_kernel<<<dim3(HID / 2, NSTREAMS), C_IN>>>(ow0, ow1);

    int smem_e = 9216 + 3 * 16384;   // 58368
    cudaFuncSetAttribute(embed_kernel, cudaFuncAttributeMaxDynamicSharedMemorySize, smem_e);
    embed_kernel<<<dim3(NTOK / 64, 16), 256, smem_e>>>(x0, x1, eb0, eb1);

    int smem_a = 2 * 65536;
    cudaFuncSetAttribute(attn_kernel, cudaFuncAttributeMaxDynamicSharedMemorySize, smem_a);
    attn_kernel<<<dim3(NTOK / 128, NB, NSTREAMS), 256, smem_a>>>(x0, x1, ob0, ob1, out);
}